// round 2
// baseline (speedup 1.0000x reference)
#include <cuda_runtime.h>
#include <math.h>

#define NN   6144
#define BSET 256
#define G    24
#define DIN  128
#define EFF  512
#define DH   64
#define NH   8
#define QKV_W 1536   // q|k|v concatenated per node

typedef unsigned long long u64;

__device__ __forceinline__ u64 pack2(float lo, float hi) {
    u64 r; asm("mov.b64 %0,{%1,%2};" : "=l"(r) : "f"(lo), "f"(hi)); return r;
}
__device__ __forceinline__ u64 fma2(u64 a, u64 b, u64 c) {
    u64 d; asm("fma.rn.f32x2 %0,%1,%2,%3;" : "=l"(d) : "l"(a), "l"(b), "l"(c)); return d;
}
__device__ __forceinline__ void unpack2(u64 v, float& lo, float& hi) {
    asm("mov.b64 {%0,%1},%2;" : "=f"(lo), "=f"(hi) : "l"(v));
}

// ---------------- scratch (device globals; no allocation allowed) ----------
__device__ float g_qkv[NN * QKV_W];   // ~37.7 MB
__device__ float g_h[NN * DH];
__device__ float g_sum[DIN];
__device__ float g_sumsq[DIN];
__device__ float g_hsum[DH];
__device__ float g_hsumsq[DH];

// ---------------- K0: zero accumulators ------------------------------------
__global__ void k_zero() {
    int t = threadIdx.x;
    if (t < DIN) { g_sum[t] = 0.f; g_sumsq[t] = 0.f; }
    if (t < DH)  { g_hsum[t] = 0.f; g_hsumsq[t] = 0.f; }
}

// ---------------- K1: per-channel sum/sumsq of x ----------------------------
__global__ void k_xstats(const float* __restrict__ x) {
    int c  = threadIdx.x;          // 128 threads = channels
    int r0 = blockIdx.x * 128;     // 48 blocks * 128 rows
    float s = 0.f, s2 = 0.f;
    for (int r = 0; r < 128; r++) {
        float v = x[(r0 + r) * DIN + c];
        s += v; s2 += v * v;
    }
    atomicAdd(&g_sum[c], s);
    atomicAdd(&g_sumsq[c], s2);
}

// ---------------- K2: QKV GEMM (xn @ W^T + b), f32x2 packed -----------------
// grid (48, 12): 48 node tiles of 128, 12 output chunks of 128 (3*512 outputs)
// smem: xs[128][129], ws[128][129] (odd pitch -> low-conflict scalar LDS)
#define P129 129
__global__ void __launch_bounds__(256, 1)
k_qkv(const float* __restrict__ x,
      const float* __restrict__ nq_w, const float* __restrict__ nq_b,
      const float* __restrict__ nq_ms,
      const float* __restrict__ wq, const float* __restrict__ bq,
      const float* __restrict__ wk, const float* __restrict__ bk,
      const float* __restrict__ wv, const float* __restrict__ bv) {
    extern __shared__ float sm[];
    float* xs  = sm;                       // [128][129]
    float* ws  = xs + 128 * P129;          // [128][129]
    float* Axn = ws + 128 * P129;          // [128]
    float* Bxn = Axn + 128;                // [128]

    int tid = threadIdx.x;                 // 256
    int m0  = blockIdx.x * 128;
    int oc  = blockIdx.y * 128;            // 0..1535
    int mat = oc >> 9;                     // 0=q, 1=k, 2=v
    int o0  = oc & 511;
    const float* W    = mat == 0 ? wq : (mat == 1 ? wk : wv);
    const float* bias = mat == 0 ? bq : (mat == 1 ? bk : bv);

    if (tid < DIN) {
        const float invN = 1.0f / NN;
        float mean = g_sum[tid] * invN;
        float ex2  = g_sumsq[tid] * invN;
        float mm   = mean * nq_ms[tid];
        float var  = ex2 - 2.f * mm * mean + mm * mm;
        float rinv = rsqrtf(var + 1e-5f);
        Axn[tid] = nq_w[tid] * rinv;
        Bxn[tid] = nq_b[tid] - nq_w[tid] * rinv * mm;
    }
    __syncthreads();

    // Load x tile (normalized in-flight) + weight tile. Coalesced f4 reads.
    const float4* xg = (const float4*)x;
    const float4* Wg = (const float4*)W;
    for (int i = tid; i < 128 * 32; i += 256) {
        int row = i >> 5, kq = i & 31;
        int c = kq * 4;
        float4 v = xg[(m0 + row) * 32 + kq];
        v.x = fmaf(v.x, Axn[c],     Bxn[c]);
        v.y = fmaf(v.y, Axn[c + 1], Bxn[c + 1]);
        v.z = fmaf(v.z, Axn[c + 2], Bxn[c + 2]);
        v.w = fmaf(v.w, Axn[c + 3], Bxn[c + 3]);
        float* dx = xs + row * P129 + c;
        dx[0] = v.x; dx[1] = v.y; dx[2] = v.z; dx[3] = v.w;
        float4 w = Wg[(o0 + row) * 32 + kq];
        float* dw = ws + row * P129 + c;
        dw[0] = w.x; dw[1] = w.y; dw[2] = w.z; dw[3] = w.w;
    }
    __syncthreads();

    int w    = tid >> 5, lane = tid & 31;
    int mb = (w >> 2) * 64 + (lane >> 2) * 8;   // 8 contiguous rows per thread
    int nb = (w & 3) * 32 + (lane & 3) * 8;     // 8 contiguous cols per thread

    u64 acc[8][4];
    #pragma unroll
    for (int r = 0; r < 8; r++)
        #pragma unroll
        for (int c2 = 0; c2 < 4; c2++) acc[r][c2] = 0ull;

    #pragma unroll 4
    for (int k = 0; k < 128; k++) {
        u64 b2[4];
        #pragma unroll
        for (int c2 = 0; c2 < 4; c2++)
            b2[c2] = pack2(ws[(nb + 2 * c2) * P129 + k],
                           ws[(nb + 2 * c2 + 1) * P129 + k]);
        #pragma unroll
        for (int r = 0; r < 8; r++) {
            float av = xs[(mb + r) * P129 + k];
            u64 a2 = pack2(av, av);
            #pragma unroll
            for (int c2 = 0; c2 < 4; c2++)
                acc[r][c2] = fma2(a2, b2[c2], acc[r][c2]);
        }
    }

    #pragma unroll
    for (int r = 0; r < 8; r++) {
        float o[8];
        #pragma unroll
        for (int c2 = 0; c2 < 4; c2++) unpack2(acc[r][c2], o[2 * c2], o[2 * c2 + 1]);
        #pragma unroll
        for (int j = 0; j < 8; j++) o[j] += bias[o0 + nb + j];
        float4* dst = (float4*)(g_qkv + (size_t)(m0 + mb + r) * QKV_W + oc + nb);
        dst[0] = make_float4(o[0], o[1], o[2], o[3]);
        dst[1] = make_float4(o[4], o[5], o[6], o[7]);
    }
}

// ---------------- K3: per-set dense attention + residual + h-stats ----------
// smem: q[24][512] natural, v[24][512] natural, kT as float4 [128 grp][25 slots]
__global__ void __launch_bounds__(256, 1)
k_attn(const float* __restrict__ x) {
    extern __shared__ float sm[];
    float* q     = sm;                 // 24*512 = 12288
    float* v     = q + 12288;          // 12288
    float* kt    = v + 12288;          // 128*100 = 12800 (pitch 25 float4)
    float* alpha = kt + 12800;         // 8*24*24 = 4608
    float* hs    = alpha + 4608;       // 24*64 = 1536

    int tid = threadIdx.x;             // 256
    int n0  = blockIdx.x * G;

    const float4* src = (const float4*)(g_qkv + (size_t)n0 * QKV_W);
    float4* q4  = (float4*)q;
    float4* v4  = (float4*)v;
    float4* kt4 = (float4*)kt;

    // coalesced loads; kT store conflict-free (pitch 25 f4, lanes vary g)
    for (int i = tid; i < 24 * 128; i += 256) {
        int n = i >> 7, c = i & 127;
        q4[n * 128 + c] = src[n * 384 + c];
        v4[n * 128 + c] = src[n * 384 + 256 + c];
        kt4[c * 25 + n] = src[n * 384 + 128 + c];   // kt4[group][slot s]
    }
    __syncthreads();

    // logits: thread = (h, d, sg) computes 3 s-values sharing q loads
    for (int idx = tid; idx < NH * G * 8; idx += 256) {
        int h   = idx / 192;
        int rem = idx - h * 192;
        int d = rem >> 3, sg = rem & 7;
        const float4* qp = q4 + d * 128 + h * 16;
        float a0 = 0.f, a1 = 0.f, a2v = 0.f;
        #pragma unroll
        for (int j = 0; j < 16; j++) {
            float4 qq = qp[j];
            const float4* kp = kt4 + (h * 16 + j) * 25 + sg * 3;
            float4 k0 = kp[0], k1 = kp[1], k2 = kp[2];
            a0  += qq.x * k0.x + qq.y * k0.y + qq.z * k0.z + qq.w * k0.w;
            a1  += qq.x * k1.x + qq.y * k1.y + qq.z * k1.z + qq.w * k1.w;
            a2v += qq.x * k2.x + qq.y * k2.y + qq.z * k2.z + qq.w * k2.w;
        }
        float* arow = alpha + (h * G + d) * G + sg * 3;
        arow[0] = a0 * 0.125f; arow[1] = a1 * 0.125f; arow[2] = a2v * 0.125f;
    }
    __syncthreads();

    // softmax per (h,d) over 24 sources
    if (tid < NH * G) {
        float* row = alpha + tid * G;
        float m = row[0];
        #pragma unroll
        for (int s = 1; s < G; s++) m = fmaxf(m, row[s]);
        float e[G], sum = 0.f;
        #pragma unroll
        for (int s = 0; s < G; s++) { e[s] = expf(row[s] - m); sum += e[s]; }
        float inv = 1.0f / (sum + 1e-16f);
        #pragma unroll
        for (int s = 0; s < G; s++) row[s] = e[s] * inv;
    }
    __syncthreads();

    // aggregate (mean over heads) + fold residual; vectorized float4 over c
    for (int idx = tid; idx < G * 16; idx += 256) {
        int d = idx >> 4, c4 = idx & 15;
        float4 acc = make_float4(0.f, 0.f, 0.f, 0.f);
        #pragma unroll
        for (int h = 0; h < NH; h++) {
            const float* ar  = alpha + (h * G + d) * G;
            const float4* vp = v4 + h * 16 + c4;
            #pragma unroll
            for (int s = 0; s < G; s++) {
                float a = ar[s];
                float4 vv = vp[s * 128];
                acc.x = fmaf(a, vv.x, acc.x);
                acc.y = fmaf(a, vv.y, acc.y);
                acc.z = fmaf(a, vv.z, acc.z);
                acc.w = fmaf(a, vv.w, acc.w);
            }
        }
        const float4* xr = (const float4*)(x + (size_t)(n0 + d) * DIN);
        float4 r0 = xr[c4], r1 = xr[16 + c4];
        acc.x = acc.x * 0.125f + r0.x + r1.x;
        acc.y = acc.y * 0.125f + r0.y + r1.y;
        acc.z = acc.z * 0.125f + r0.z + r1.z;
        acc.w = acc.w * 0.125f + r0.w + r1.w;
        ((float4*)(g_h + (size_t)(n0 + d) * DH))[c4] = acc;
        ((float4*)(hs + d * DH))[c4] = acc;
    }
    __syncthreads();

    if (tid < DH) {
        float s = 0.f, s2 = 0.f;
        #pragma unroll
        for (int d = 0; d < G; d++) { float w = hs[d * DH + tid]; s += w; s2 += w * w; }
        atomicAdd(&g_hsum[tid], s);
        atomicAdd(&g_hsumsq[tid], s2);
    }
}

__device__ __forceinline__ float gelu_exact(float v) {
    return 0.5f * v * (1.0f + erff(v * 0.70710678118654752f));
}

// ---------------- K4: global norm + PFF + per-set norm + score + pooling ----
__global__ void __launch_bounds__(256)
k_final(const float* __restrict__ x,
        const float* __restrict__ no_w, const float* __restrict__ no_b,
        const float* __restrict__ no_ms,
        const float* __restrict__ o_w1, const float* __restrict__ o_b1,
        const float* __restrict__ o_w2, const float* __restrict__ o_b2,
        const float* __restrict__ pn_w, const float* __restrict__ pn_b,
        const float* __restrict__ pn_ms,
        const float* __restrict__ p_w1, const float* __restrict__ p_b1,
        const float* __restrict__ p_w2, const float* __restrict__ p_b2,
        float* __restrict__ out) {
    __shared__ float hs[G * DH], hn[G * DH], t1[G * DH], h2[G * DH];
    __shared__ float a2[DH], b2[DH], cm[DH], cr[DH];
    __shared__ float score[G], wsf[G];

    int tid = threadIdx.x;   // 256
    int n0  = blockIdx.x * G;

    for (int i = tid; i < G * DH; i += 256) hs[i] = g_h[n0 * DH + i];

    if (tid < DH) {
        const float invN = 1.0f / NN;
        float mean = g_hsum[tid] * invN;
        float ex2  = g_hsumsq[tid] * invN;
        float mm   = mean * no_ms[tid];
        float var  = ex2 - 2.f * mm * mean + mm * mm;
        float rinv = rsqrtf(var + 1e-5f);
        a2[tid] = no_w[tid] * rinv;
        b2[tid] = no_b[tid] - no_w[tid] * rinv * mm;
    }
    __syncthreads();

    for (int i = tid; i < G * DH; i += 256) {
        int c = i & 63;
        hn[i] = fmaf(hs[i], a2[c], b2[c]);
    }
    __syncthreads();

    // t1 = gelu(hn @ o_w1^T + o_b1)
    for (int i = tid; i < G * DH; i += 256) {
        int d = i >> 6, j = i & 63;
        float acc = o_b1[j];
        const float* hr = hn + d * DH;
        const float* wr = o_w1 + j * DH;
        #pragma unroll 8
        for (int c = 0; c < DH; c++) acc = fmaf(hr[c], wr[c], acc);
        t1[i] = gelu_exact(acc);
    }
    __syncthreads();

    // h2 = h + t1 @ o_w2^T + o_b2
    for (int i = tid; i < G * DH; i += 256) {
        int d = i >> 6, c = i & 63;
        float acc = o_b2[c];
        const float* tr = t1 + d * DH;
        const float* wr = o_w2 + c * DH;
        #pragma unroll 8
        for (int j = 0; j < DH; j++) acc = fmaf(tr[j], wr[j], acc);
        h2[i] = hs[i] + acc;
    }
    __syncthreads();

    // per-set GraphNorm on h2
    if (tid < DH) {
        int c = tid;
        float m = 0.f;
        #pragma unroll
        for (int d = 0; d < G; d++) m += h2[d * DH + c];
        m *= (1.0f / G);
        float mm = m * pn_ms[c];
        float vv = 0.f;
        #pragma unroll
        for (int d = 0; d < G; d++) { float t = h2[d * DH + c] - mm; vv += t * t; }
        vv *= (1.0f / G);
        cm[c] = mm;
        cr[c] = pn_w[c] * rsqrtf(vv + 1e-5f);
    }
    __syncthreads();

    for (int i = tid; i < G * DH; i += 256) {
        int c = i & 63;
        hn[i] = fmaf(h2[i] - cm[c], cr[c], pn_b[c]);
    }
    __syncthreads();

    // t2 = gelu(hn2 @ p_w1^T + p_b1)
    for (int i = tid; i < G * DH; i += 256) {
        int d = i >> 6, j = i & 63;
        float acc = p_b1[j];
        const float* hr = hn + d * DH;
        const float* wr = p_w1 + j * DH;
        #pragma unroll 8
        for (int c = 0; c < DH; c++) acc = fmaf(hr[c], wr[c], acc);
        t1[i] = gelu_exact(acc);
    }
    __syncthreads();

    if (tid < G) {
        float acc = p_b2[0];
        const float* tr = t1 + tid * DH;
        #pragma unroll 8
        for (int j = 0; j < DH; j++) acc = fmaf(tr[j], p_w2[j], acc);
        score[tid] = acc;
    }
    __syncthreads();

    if (tid == 0) {
        float m = score[0];
        #pragma unroll
        for (int d = 1; d < G; d++) m = fmaxf(m, score[d]);
        float sum = 0.f;
        #pragma unroll
        for (int d = 0; d < G; d++) { wsf[d] = expf(score[d] - m); sum += wsf[d]; }
        float inv = 1.0f / (sum + 1e-16f);
        #pragma unroll
        for (int d = 0; d < G; d++) wsf[d] *= inv;
    }
    __syncthreads();

    if (tid < DIN) {
        float acc = 0.f;
        #pragma unroll
        for (int d = 0; d < G; d++)
            acc = fmaf(wsf[d], x[(size_t)(n0 + d) * DIN + tid], acc);
        out[blockIdx.x * DIN + tid] = acc;
    }
}

// ---------------- launch -----------------------------------------------------
extern "C" void kernel_launch(void* const* d_in, const int* in_sizes, int n_in,
                              void* d_out, int out_size) {
    const float* x     = (const float*)d_in[0];
    // d_in[1..3]: edge_index / ptr / batch — deterministic block-dense, unused.
    const float* nq_w  = (const float*)d_in[4];
    const float* nq_b  = (const float*)d_in[5];
    const float* nq_ms = (const float*)d_in[6];
    const float* wq    = (const float*)d_in[7];
    const float* bq    = (const float*)d_in[8];
    const float* wk    = (const float*)d_in[9];
    const float* bk    = (const float*)d_in[10];
    const float* wv    = (const float*)d_in[11];
    const float* bv    = (const float*)d_in[12];
    const float* no_w  = (const float*)d_in[13];
    const float* no_b  = (const float*)d_in[14];
    const float* no_ms = (const float*)d_in[15];
    const float* o_w1  = (const float*)d_in[16];
    const float* o_b1  = (const float*)d_in[17];
    const float* o_w2  = (const float*)d_in[18];
    const float* o_b2  = (const float*)d_in[19];
    const float* pn_w  = (const float*)d_in[20];
    const float* pn_b  = (const float*)d_in[21];
    const float* pn_ms = (const float*)d_in[22];
    const float* p_w1  = (const float*)d_in[23];
    const float* p_b1  = (const float*)d_in[24];
    const float* p_w2  = (const float*)d_in[25];
    const float* p_b2  = (const float*)d_in[26];
    float* out = (float*)d_out;

    const int smem_qkv  = (128 * P129 * 2 + 256) * 4;                       // 133,120 B
    const int smem_attn = (12288 + 12288 + 12800 + 4608 + 1536) * 4;        // 174,080 B
    cudaFuncSetAttribute(k_qkv,  cudaFuncAttributeMaxDynamicSharedMemorySize, smem_qkv);
    cudaFuncSetAttribute(k_attn, cudaFuncAttributeMaxDynamicSharedMemorySize, smem_attn);

    k_zero<<<1, 384>>>();
    k_xstats<<<48, 128>>>(x);
    k_qkv<<<dim3(48, 12), 256, smem_qkv>>>(x, nq_w, nq_b, nq_ms,
                                           wq, bq, wk, bk, wv, bv);
    k_attn<<<256, 256, smem_attn>>>(x);
    k_final<<<256, 256>>>(x, no_w, no_b, no_ms,
                          o_w1, o_b1, o_w2, o_b2,
                          pn_w, pn_b, pn_ms,
                          p_w1, p_b1, p_w2, p_b2, out);
}

// round 3
// speedup vs baseline: 3.5812x; 3.5812x over previous
#include <cuda_runtime.h>
#include <math.h>

#define NN   6144
#define BSET 256
#define G    24
#define DIN  128
#define EFF  512
#define DH   64
#define NH   8
#define QKV_W 1536

typedef unsigned long long u64;

__device__ __forceinline__ u64 pack2(float lo, float hi) {
    u64 r; asm("mov.b64 %0,{%1,%2};" : "=l"(r) : "f"(lo), "f"(hi)); return r;
}
__device__ __forceinline__ u64 fma2(u64 a, u64 b, u64 c) {
    u64 d; asm("fma.rn.f32x2 %0,%1,%2,%3;" : "=l"(d) : "l"(a), "l"(b), "l"(c)); return d;
}
__device__ __forceinline__ void unpack2(u64 v, float& lo, float& hi) {
    asm("mov.b64 {%0,%1},%2;" : "=f"(lo), "=f"(hi) : "l"(v));
}

// ---------------- device scratch --------------------------------------------
__device__ float g_qkv[NN * QKV_W];    // 37.7 MB
__device__ float g_part[NN * EFF];     // per-head attention partials, 12.6 MB
__device__ float g_h[NN * DH];
__device__ float g_sum[DIN];
__device__ float g_sumsq[DIN];
__device__ float g_hsum[DH];
__device__ float g_hsumsq[DH];

// ---------------- K0: zero stat accumulators --------------------------------
__global__ void k_zero() {
    int t = threadIdx.x;
    if (t < DIN) { g_sum[t] = 0.f; g_sumsq[t] = 0.f; }
    if (t < DH)  { g_hsum[t] = 0.f; g_hsumsq[t] = 0.f; }
}

// ---------------- K1: per-channel sum/sumsq of x (96 blocks x 64 rows) ------
__global__ void __launch_bounds__(256)
k_xstats(const float* __restrict__ x) {
    __shared__ float smS[8 * 128], smQ[8 * 128];
    int t  = threadIdx.x;
    int c4 = t & 31;           // 32 float4 groups = 128 channels
    int rs = t >> 5;           // 8 row slots
    int r0 = blockIdx.x * 64;

    const float4* xg = (const float4*)x;
    float4 s = make_float4(0.f, 0.f, 0.f, 0.f);
    float4 q = make_float4(0.f, 0.f, 0.f, 0.f);
    #pragma unroll
    for (int r = rs; r < 64; r += 8) {
        float4 v = xg[(size_t)(r0 + r) * 32 + c4];
        s.x += v.x; s.y += v.y; s.z += v.z; s.w += v.w;
        q.x += v.x * v.x; q.y += v.y * v.y; q.z += v.z * v.z; q.w += v.w * v.w;
    }
    ((float4*)smS)[rs * 32 + c4] = s;
    ((float4*)smQ)[rs * 32 + c4] = q;
    __syncthreads();
    if (t < 128) {
        float ss = 0.f, qq = 0.f;
        #pragma unroll
        for (int j = 0; j < 8; j++) { ss += smS[j * 128 + t]; qq += smQ[j * 128 + t]; }
        atomicAdd(&g_sum[t], ss);
        atomicAdd(&g_sumsq[t], qq);
    }
}

// ---------------- K2: QKV GEMM, 128x128 tile, 512 threads, f32x2 ------------
#define P129 129
__global__ void __launch_bounds__(512, 1)
k_qkv(const float* __restrict__ x,
      const float* __restrict__ nq_w, const float* __restrict__ nq_b,
      const float* __restrict__ nq_ms,
      const float* __restrict__ wq, const float* __restrict__ bq,
      const float* __restrict__ wk, const float* __restrict__ bk,
      const float* __restrict__ wv, const float* __restrict__ bv) {
    extern __shared__ float sm[];
    float* xs  = sm;                       // [128][129]
    float* ws  = xs + 128 * P129;          // [128][129]
    float* Axn = ws + 128 * P129;          // [128]
    float* Bxn = Axn + 128;                // [128]

    int tid = threadIdx.x;                 // 512
    int m0  = blockIdx.x * 128;
    int oc  = blockIdx.y * 128;
    int mat = oc >> 9;
    int o0  = oc & 511;
    const float* W    = mat == 0 ? wq : (mat == 1 ? wk : wv);
    const float* bias = mat == 0 ? bq : (mat == 1 ? bk : bv);

    if (tid < DIN) {
        const float invN = 1.0f / NN;
        float mean = g_sum[tid] * invN;
        float ex2  = g_sumsq[tid] * invN;
        float mm   = mean * nq_ms[tid];
        float var  = ex2 - 2.f * mm * mean + mm * mm;
        float rinv = rsqrtf(var + 1e-5f);
        Axn[tid] = nq_w[tid] * rinv;
        Bxn[tid] = nq_b[tid] - nq_w[tid] * rinv * mm;
    }
    __syncthreads();

    const float4* xg = (const float4*)x;
    const float4* Wg = (const float4*)W;
    #pragma unroll
    for (int i = tid; i < 128 * 32; i += 512) {
        int row = i >> 5, kq = i & 31;
        int c = kq * 4;
        float4 v = xg[(size_t)(m0 + row) * 32 + kq];
        v.x = fmaf(v.x, Axn[c],     Bxn[c]);
        v.y = fmaf(v.y, Axn[c + 1], Bxn[c + 1]);
        v.z = fmaf(v.z, Axn[c + 2], Bxn[c + 2]);
        v.w = fmaf(v.w, Axn[c + 3], Bxn[c + 3]);
        float* dx = xs + row * P129 + c;
        dx[0] = v.x; dx[1] = v.y; dx[2] = v.z; dx[3] = v.w;
        float4 w = Wg[(size_t)(o0 + row) * 32 + kq];
        float* dw = ws + row * P129 + c;
        dw[0] = w.x; dw[1] = w.y; dw[2] = w.z; dw[3] = w.w;
    }
    __syncthreads();

    int w    = tid >> 5, lane = tid & 31;
    int mb = (((w >> 2) << 2) | (lane >> 3)) * 8;   // 16 row-groups of 8
    int nb = (((w & 3) << 3) | (lane & 7)) * 4;     // 32 col-groups of 4

    u64 acc[8][2];
    #pragma unroll
    for (int r = 0; r < 8; r++) { acc[r][0] = 0ull; acc[r][1] = 0ull; }

    #pragma unroll 4
    for (int k = 0; k < 128; k++) {
        u64 b0 = pack2(ws[nb * P129 + k],       ws[(nb + 1) * P129 + k]);
        u64 b1 = pack2(ws[(nb + 2) * P129 + k], ws[(nb + 3) * P129 + k]);
        #pragma unroll
        for (int r = 0; r < 8; r++) {
            float av = xs[(mb + r) * P129 + k];
            u64 a2 = pack2(av, av);
            acc[r][0] = fma2(a2, b0, acc[r][0]);
            acc[r][1] = fma2(a2, b1, acc[r][1]);
        }
    }

    float bs0 = bias[o0 + nb], bs1 = bias[o0 + nb + 1];
    float bs2 = bias[o0 + nb + 2], bs3 = bias[o0 + nb + 3];
    #pragma unroll
    for (int r = 0; r < 8; r++) {
        float o0f, o1f, o2f, o3f;
        unpack2(acc[r][0], o0f, o1f);
        unpack2(acc[r][1], o2f, o3f);
        float4* dst = (float4*)(g_qkv + (size_t)(m0 + mb + r) * QKV_W + oc + nb);
        *dst = make_float4(o0f + bs0, o1f + bs1, o2f + bs2, o3f + bs3);
    }
}

// ---------------- K3: per-(set,head) attention -> g_part --------------------
// grid 2048 = 256 sets * 8 heads, 128 threads, ~21KB static smem
__global__ void __launch_bounds__(128)
k_attn() {
    __shared__ float4 q4h[24 * 16];       // q [d][c4]
    __shared__ float4 kt4[16 * 25];       // k transposed [c4 group][s] pitch 25
    __shared__ float4 v4h[24 * 16];       // v [s][c4]
    __shared__ float  alpha[24 * 24];

    int tid = threadIdx.x;
    int set = blockIdx.x >> 3;
    int h   = blockIdx.x & 7;
    int n0  = set * G;

    const float4* src4 = (const float4*)g_qkv + (size_t)n0 * 384;
    #pragma unroll
    for (int i = tid; i < 24 * 16; i += 128) {
        int n = i >> 4, c4 = i & 15;
        q4h[i] = src4[n * 384 + h * 16 + c4];
        v4h[i] = src4[n * 384 + 256 + h * 16 + c4];
        kt4[c4 * 25 + n] = src4[n * 384 + 128 + h * 16 + c4];
    }
    __syncthreads();

    // logits: (d,s) items
    for (int idx = tid; idx < G * G; idx += 128) {
        int d = idx / G, s = idx - d * G;
        float acc = 0.f;
        #pragma unroll
        for (int j = 0; j < 16; j++) {
            float4 qq = q4h[d * 16 + j];
            float4 kk = kt4[j * 25 + s];
            acc += qq.x * kk.x + qq.y * kk.y + qq.z * kk.z + qq.w * kk.w;
        }
        alpha[idx] = acc * 0.125f;   // / sqrt(64)
    }
    __syncthreads();

    // softmax per destination d over 24 sources
    if (tid < G) {
        float* row = alpha + tid * G;
        float m = row[0];
        #pragma unroll
        for (int s = 1; s < G; s++) m = fmaxf(m, row[s]);
        float e[G], sum = 0.f;
        #pragma unroll
        for (int s = 0; s < G; s++) { e[s] = expf(row[s] - m); sum += e[s]; }
        float inv = 1.0f / (sum + 1e-16f);
        #pragma unroll
        for (int s = 0; s < G; s++) row[s] = e[s] * inv;
    }
    __syncthreads();

    // aggregate: out[d][c] = (1/8) * sum_s alpha[d][s] * v[s][c]
    float4* part4 = (float4*)g_part;
    #pragma unroll
    for (int i = tid; i < G * 16; i += 128) {
        int d = i >> 4, c4 = i & 15;
        float4 acc = make_float4(0.f, 0.f, 0.f, 0.f);
        const float* ar = alpha + d * G;
        #pragma unroll
        for (int s = 0; s < G; s++) {
            float a = ar[s];
            float4 vv = v4h[s * 16 + c4];
            acc.x = fmaf(a, vv.x, acc.x);
            acc.y = fmaf(a, vv.y, acc.y);
            acc.z = fmaf(a, vv.z, acc.z);
            acc.w = fmaf(a, vv.w, acc.w);
        }
        acc.x *= 0.125f; acc.y *= 0.125f; acc.z *= 0.125f; acc.w *= 0.125f;
        part4[(size_t)(n0 + d) * 128 + h * 16 + c4] = acc;
    }
}

// ---------------- K3b: sum heads + fold residual + h stats ------------------
__global__ void __launch_bounds__(256)
k_hres(const float* __restrict__ x) {
    __shared__ float smS[16 * 64], smQ[16 * 64];
    int t  = threadIdx.x;
    int c4 = t & 15;           // 16 groups = 64 channels
    int rs = t >> 4;           // 16 row slots
    int r0 = blockIdx.x * 128;

    const float4* part4 = (const float4*)g_part;
    const float4* xg    = (const float4*)x;
    float4* h4 = (float4*)g_h;

    float4 s = make_float4(0.f, 0.f, 0.f, 0.f);
    float4 q = make_float4(0.f, 0.f, 0.f, 0.f);
    #pragma unroll
    for (int r = rs; r < 128; r += 16) {
        size_t row = r0 + r;
        float4 a = make_float4(0.f, 0.f, 0.f, 0.f);
        #pragma unroll
        for (int hh = 0; hh < NH; hh++) {
            float4 p = part4[row * 128 + hh * 16 + c4];
            a.x += p.x; a.y += p.y; a.z += p.z; a.w += p.w;
        }
        float4 x0 = xg[row * 32 + c4];
        float4 x1 = xg[row * 32 + 16 + c4];
        a.x += x0.x + x1.x; a.y += x0.y + x1.y;
        a.z += x0.z + x1.z; a.w += x0.w + x1.w;
        h4[row * 16 + c4] = a;
        s.x += a.x; s.y += a.y; s.z += a.z; s.w += a.w;
        q.x += a.x * a.x; q.y += a.y * a.y; q.z += a.z * a.z; q.w += a.w * a.w;
    }
    ((float4*)smS)[rs * 16 + c4] = s;
    ((float4*)smQ)[rs * 16 + c4] = q;
    __syncthreads();
    if (t < 64) {
        float ss = 0.f, qq = 0.f;
        #pragma unroll
        for (int j = 0; j < 16; j++) { ss += smS[j * 64 + t]; qq += smQ[j * 64 + t]; }
        atomicAdd(&g_hsum[t], ss);
        atomicAdd(&g_hsumsq[t], qq);
    }
}

__device__ __forceinline__ float gelu_exact(float v) {
    return 0.5f * v * (1.0f + erff(v * 0.70710678118654752f));
}

// ---------------- K4: global norm + PFF + per-set norm + score + pooling ----
// weights staged in smem TRANSPOSED with pitch 65 (conflict-free)
#define WP 65
__global__ void __launch_bounds__(256)
k_final(const float* __restrict__ x,
        const float* __restrict__ no_w, const float* __restrict__ no_b,
        const float* __restrict__ no_ms,
        const float* __restrict__ o_w1, const float* __restrict__ o_b1,
        const float* __restrict__ o_w2, const float* __restrict__ o_b2,
        const float* __restrict__ pn_w, const float* __restrict__ pn_b,
        const float* __restrict__ pn_ms,
        const float* __restrict__ p_w1, const float* __restrict__ p_b1,
        const float* __restrict__ p_w2, const float* __restrict__ p_b2,
        float* __restrict__ out) {
    extern __shared__ float dsm[];
    float* w1T  = dsm;                  // [64][65]  w1T[in*65+out] = o_w1[out][in]
    float* w2T  = w1T + 64 * WP;        // [64][65]
    float* pw1T = w2T + 64 * WP;        // [64][65]
    float* hs   = pw1T + 64 * WP;       // [24*64]
    float* hn   = hs + G * DH;
    float* t1   = hn + G * DH;
    float* h2   = t1 + G * DH;
    float* a2   = h2 + G * DH;          // [64] x4
    float* b2   = a2 + DH;
    float* cm   = b2 + DH;
    float* cr   = cm + DH;
    float* b1s  = cr + DH;              // biases [64] x3 + pw2 [64]
    float* b2s  = b1s + DH;
    float* pb1s = b2s + DH;
    float* pw2s = pb1s + DH;
    float* score = pw2s + DH;           // [24]
    float* wsf   = score + G;           // [24]

    int tid = threadIdx.x;   // 256
    int n0  = blockIdx.x * G;

    // stage weights transposed (coalesced gmem read, conflict-free smem store)
    for (int i = tid; i < 64 * 64; i += 256) {
        int j = i >> 6, c = i & 63;     // j = out row, c = in col
        w1T[c * WP + j]  = o_w1[i];
        w2T[c * WP + j]  = o_w2[i];
        pw1T[c * WP + j] = p_w1[i];
    }
    if (tid < DH) {
        b1s[tid] = o_b1[tid]; b2s[tid] = o_b2[tid];
        pb1s[tid] = p_b1[tid]; pw2s[tid] = p_w2[tid];
        const float invN = 1.0f / NN;
        float mean = g_hsum[tid] * invN;
        float ex2  = g_hsumsq[tid] * invN;
        float mm   = mean * no_ms[tid];
        float var  = ex2 - 2.f * mm * mean + mm * mm;
        float rinv = rsqrtf(var + 1e-5f);
        a2[tid] = no_w[tid] * rinv;
        b2[tid] = no_b[tid] - no_w[tid] * rinv * mm;
    }
    for (int i = tid; i < G * DH; i += 256) hs[i] = g_h[(size_t)n0 * DH + i];
    __syncthreads();

    for (int i = tid; i < G * DH; i += 256) {
        int c = i & 63;
        hn[i] = fmaf(hs[i], a2[c], b2[c]);
    }
    __syncthreads();

    // t1 = gelu(hn @ o_w1^T + b1)
    for (int i = tid; i < G * DH; i += 256) {
        int d = i >> 6, j = i & 63;
        float acc = b1s[j];
        const float* hr = hn + d * DH;
        #pragma unroll 16
        for (int c = 0; c < DH; c++) acc = fmaf(hr[c], w1T[c * WP + j], acc);
        t1[i] = gelu_exact(acc);
    }
    __syncthreads();

    // h2 = hs + t1 @ o_w2^T + b2
    for (int i = tid; i < G * DH; i += 256) {
        int d = i >> 6, c = i & 63;
        float acc = b2s[c];
        const float* tr = t1 + d * DH;
        #pragma unroll 16
        for (int j = 0; j < DH; j++) acc = fmaf(tr[j], w2T[j * WP + c], acc);
        h2[i] = hs[i] + acc;
    }
    __syncthreads();

    // per-set GraphNorm on h2
    if (tid < DH) {
        int c = tid;
        float m = 0.f;
        #pragma unroll
        for (int d = 0; d < G; d++) m += h2[d * DH + c];
        m *= (1.0f / G);
        float mm = m * pn_ms[c];
        float vv = 0.f;
        #pragma unroll
        for (int d = 0; d < G; d++) { float t = h2[d * DH + c] - mm; vv += t * t; }
        vv *= (1.0f / G);
        cm[c] = mm;
        cr[c] = pn_w[c] * rsqrtf(vv + 1e-5f);
    }
    __syncthreads();

    for (int i = tid; i < G * DH; i += 256) {
        int c = i & 63;
        hn[i] = fmaf(h2[i] - cm[c], cr[c], pn_b[c]);
    }
    __syncthreads();

    // t2 = gelu(hn @ p_w1^T + pb1)
    for (int i = tid; i < G * DH; i += 256) {
        int d = i >> 6, j = i & 63;
        float acc = pb1s[j];
        const float* hr = hn + d * DH;
        #pragma unroll 16
        for (int c = 0; c < DH; c++) acc = fmaf(hr[c], pw1T[c * WP + j], acc);
        t1[i] = gelu_exact(acc);
    }
    __syncthreads();

    if (tid < G) {
        float acc = p_b2[0];
        const float* tr = t1 + tid * DH;
        #pragma unroll 16
        for (int j = 0; j < DH; j++) acc = fmaf(tr[j], pw2s[j], acc);
        score[tid] = acc;
    }
    __syncthreads();

    if (tid == 0) {
        float m = score[0];
        #pragma unroll
        for (int d = 1; d < G; d++) m = fmaxf(m, score[d]);
        float sum = 0.f;
        #pragma unroll
        for (int d = 0; d < G; d++) { wsf[d] = expf(score[d] - m); sum += wsf[d]; }
        float inv = 1.0f / (sum + 1e-16f);
        #pragma unroll
        for (int d = 0; d < G; d++) wsf[d] *= inv;
    }
    __syncthreads();

    if (tid < DIN) {
        float acc = 0.f;
        #pragma unroll
        for (int d = 0; d < G; d++)
            acc = fmaf(wsf[d], x[(size_t)(n0 + d) * DIN + tid], acc);
        out[blockIdx.x * DIN + tid] = acc;
    }
}

// ---------------- launch -----------------------------------------------------
extern "C" void kernel_launch(void* const* d_in, const int* in_sizes, int n_in,
                              void* d_out, int out_size) {
    const float* x     = (const float*)d_in[0];
    const float* nq_w  = (const float*)d_in[4];
    const float* nq_b  = (const float*)d_in[5];
    const float* nq_ms = (const float*)d_in[6];
    const float* wq    = (const float*)d_in[7];
    const float* bq    = (const float*)d_in[8];
    const float* wk    = (const float*)d_in[9];
    const float* bk    = (const float*)d_in[10];
    const float* wv    = (const float*)d_in[11];
    const float* bv    = (const float*)d_in[12];
    const float* no_w  = (const float*)d_in[13];
    const float* no_b  = (const float*)d_in[14];
    const float* no_ms = (const float*)d_in[15];
    const float* o_w1  = (const float*)d_in[16];
    const float* o_b1  = (const float*)d_in[17];
    const float* o_w2  = (const float*)d_in[18];
    const float* o_b2  = (const float*)d_in[19];
    const float* pn_w  = (const float*)d_in[20];
    const float* pn_b  = (const float*)d_in[21];
    const float* pn_ms = (const float*)d_in[22];
    const float* p_w1  = (const float*)d_in[23];
    const float* p_b1  = (const float*)d_in[24];
    const float* p_w2  = (const float*)d_in[25];
    const float* p_b2  = (const float*)d_in[26];
    float* out = (float*)d_out;

    const int smem_qkv = (128 * P129 * 2 + 256) * 4;   // 133,120 B
    const int smem_fin = (3 * 64 * WP + 4 * G * DH + 8 * DH + 2 * G) * 4; // ~77 KB
    cudaFuncSetAttribute(k_qkv,   cudaFuncAttributeMaxDynamicSharedMemorySize, smem_qkv);
    cudaFuncSetAttribute(k_final, cudaFuncAttributeMaxDynamicSharedMemorySize, smem_fin);

    k_zero<<<1, 384>>>();
    k_xstats<<<96, 256>>>(x);
    k_qkv<<<dim3(48, 12), 512, smem_qkv>>>(x, nq_w, nq_b, nq_ms,
                                           wq, bq, wk, bk, wv, bv);
    k_attn<<<2048, 128>>>();
    k_hres<<<48, 256>>>(x);
    k_final<<<256, 256, smem_fin>>>(x, no_w, no_b, no_ms,
                                    o_w1, o_b1, o_w2, o_b2,
                                    pn_w, pn_b, pn_ms,
                                    p_w1, p_b1, p_w2, p_b2, out);
}

// round 5
// speedup vs baseline: 4.3856x; 1.2246x over previous
#include <cuda_runtime.h>
#include <cuda_bf16.h>
#include <math.h>
#include <string.h>

#define NN   6144
#define G    24
#define DIN  128
#define EFF  512
#define DH   64
#define NH   8
#define QKV_W 1536

typedef unsigned long long u64;
typedef unsigned int u32;

// ---------------- device scratch --------------------------------------------
__device__ float g_qkv[NN * QKV_W];            // 37.7 MB fp32 qkv
__device__ float g_part[NN * EFF];             // per-head attention partials
__device__ float g_h[NN * DH];
__device__ unsigned short g_xhi[NN * DIN];     // normalized x, bf16 hi
__device__ unsigned short g_xlo[NN * DIN];     // bf16 lo (residual)
__device__ unsigned short g_whi[QKV_W * DIN];  // weights q|k|v bf16 hi
__device__ unsigned short g_wlo[QKV_W * DIN];
__device__ float g_xs_part[96 * DIN];
__device__ float g_xq_part[96 * DIN];
__device__ float g_hsum[DH];
__device__ float g_hsumsq[DH];

// ---------------- PTX helpers (arch-agnostic: ldmatrix + mma.sync) ----------
__device__ __forceinline__ u32 smem_u32(const void* p) {
    u32 a;
    asm("{ .reg .u64 t; cvta.to.shared.u64 t, %1; cvt.u32.u64 %0, t; }"
        : "=r"(a) : "l"(p));
    return a;
}
__device__ __forceinline__ void ldsm_x4(u32& r0, u32& r1, u32& r2, u32& r3, u32 addr) {
    asm volatile("ldmatrix.sync.aligned.m8n8.x4.shared.b16 {%0,%1,%2,%3}, [%4];"
                 : "=r"(r0), "=r"(r1), "=r"(r2), "=r"(r3) : "r"(addr));
}
__device__ __forceinline__ void ldsm_x2(u32& r0, u32& r1, u32 addr) {
    asm volatile("ldmatrix.sync.aligned.m8n8.x2.shared.b16 {%0,%1}, [%2];"
                 : "=r"(r0), "=r"(r1) : "r"(addr));
}
__device__ __forceinline__ void mma_bf16(float* d, const u32* a, const u32* b) {
    asm volatile(
        "mma.sync.aligned.m16n8k16.row.col.f32.bf16.bf16.f32 "
        "{%0,%1,%2,%3},{%4,%5,%6,%7},{%8,%9},{%0,%1,%2,%3};"
        : "+f"(d[0]), "+f"(d[1]), "+f"(d[2]), "+f"(d[3])
        : "r"(a[0]), "r"(a[1]), "r"(a[2]), "r"(a[3]), "r"(b[0]), "r"(b[1]));
}

__device__ __forceinline__ unsigned short bf16bits(float v) {
    __nv_bfloat16 b = __float2bfloat16(v);
    unsigned short s; memcpy(&s, &b, 2); return s;
}
__device__ __forceinline__ float bf16val(float v) {
    return __bfloat162float(__float2bfloat16(v));
}

// ---------------- K1: x stats partials (96 blocks x 64 rows) ----------------
__global__ void __launch_bounds__(256)
k_xstats(const float* __restrict__ x) {
    __shared__ float smS[8 * 128], smQ[8 * 128];
    int t  = threadIdx.x;
    int c4 = t & 31;
    int rs = t >> 5;
    int r0 = blockIdx.x * 64;

    const float4* xg = (const float4*)x;
    float4 s = make_float4(0.f, 0.f, 0.f, 0.f);
    float4 q = make_float4(0.f, 0.f, 0.f, 0.f);
    #pragma unroll
    for (int r = rs; r < 64; r += 8) {
        float4 v = xg[(size_t)(r0 + r) * 32 + c4];
        s.x += v.x; s.y += v.y; s.z += v.z; s.w += v.w;
        q.x += v.x * v.x; q.y += v.y * v.y; q.z += v.z * v.z; q.w += v.w * v.w;
    }
    ((float4*)smS)[rs * 32 + c4] = s;
    ((float4*)smQ)[rs * 32 + c4] = q;
    __syncthreads();
    if (t < 128) {
        float ss = 0.f, qq = 0.f;
        #pragma unroll
        for (int j = 0; j < 8; j++) { ss += smS[j * 128 + t]; qq += smQ[j * 128 + t]; }
        g_xs_part[blockIdx.x * 128 + t] = ss;
        g_xq_part[blockIdx.x * 128 + t] = qq;
    }
}

// ---------------- K2: normalize x -> bf16 hi/lo; convert W -> bf16 hi/lo ----
__global__ void __launch_bounds__(256)
k_xnorm(const float* __restrict__ x,
        const float* __restrict__ nq_w, const float* __restrict__ nq_b,
        const float* __restrict__ nq_ms,
        const float* __restrict__ wq, const float* __restrict__ wk,
        const float* __restrict__ wv) {
    int tid = threadIdx.x;
    int b   = blockIdx.x;

    if (b == 0 && tid < DH) { g_hsum[tid] = 0.f; g_hsumsq[tid] = 0.f; }

    uint2* xh = (uint2*)g_xhi;
    uint2* xl = (uint2*)g_xlo;
    uint2* wh = (uint2*)g_whi;
    uint2* wl = (uint2*)g_wlo;

    if (b < 48) {
        __shared__ float As[128], Bs[128];
        if (tid < 128) {
            float ss = 0.f, qq = 0.f;
            #pragma unroll 8
            for (int p = 0; p < 96; p++) {
                ss += g_xs_part[p * 128 + tid];
                qq += g_xq_part[p * 128 + tid];
            }
            const float invN = 1.0f / NN;
            float mean = ss * invN;
            float ex2  = qq * invN;
            float mm   = mean * nq_ms[tid];
            float var  = ex2 - 2.f * mm * mean + mm * mm;
            float rinv = rsqrtf(var + 1e-5f);
            As[tid] = nq_w[tid] * rinv;
            Bs[tid] = nq_b[tid] - nq_w[tid] * rinv * mm;
        }
        __syncthreads();
        int r0 = b * 128;
        const float4* xg = (const float4*)x;
        for (int i = tid; i < 128 * 32; i += 256) {
            int row = i >> 5, c4 = i & 31, c = c4 * 4;
            float4 v = xg[(size_t)(r0 + row) * 32 + c4];
            float f[4];
            f[0] = fmaf(v.x, As[c],     Bs[c]);
            f[1] = fmaf(v.y, As[c + 1], Bs[c + 1]);
            f[2] = fmaf(v.z, As[c + 2], Bs[c + 2]);
            f[3] = fmaf(v.w, As[c + 3], Bs[c + 3]);
            unsigned short h[4], l[4];
            #pragma unroll
            for (int j = 0; j < 4; j++) {
                h[j] = bf16bits(f[j]);
                l[j] = bf16bits(f[j] - bf16val(f[j]));
            }
            uint2 uh, ul;
            uh.x = (u32)h[0] | ((u32)h[1] << 16); uh.y = (u32)h[2] | ((u32)h[3] << 16);
            ul.x = (u32)l[0] | ((u32)l[1] << 16); ul.y = (u32)l[2] | ((u32)l[3] << 16);
            size_t idx = (size_t)(r0 + row) * 32 + c4;
            xh[idx] = uh; xl[idx] = ul;
        }
    } else {
        int wr0 = (b - 48) * 128;
        for (int i = tid; i < 128 * 32; i += 256) {
            int row = i >> 5, c4 = i & 31;
            int gidx = wr0 + row;
            int mat = gidx >> 9, lr = gidx & 511;
            const float4* src = (const float4*)(mat == 0 ? wq : (mat == 1 ? wk : wv));
            float4 v = src[(size_t)lr * 32 + c4];
            float f[4] = {v.x, v.y, v.z, v.w};
            unsigned short h[4], l[4];
            #pragma unroll
            for (int j = 0; j < 4; j++) {
                h[j] = bf16bits(f[j]);
                l[j] = bf16bits(f[j] - bf16val(f[j]));
            }
            uint2 uh, ul;
            uh.x = (u32)h[0] | ((u32)h[1] << 16); uh.y = (u32)h[2] | ((u32)h[3] << 16);
            ul.x = (u32)l[0] | ((u32)l[1] << 16); ul.y = (u32)l[2] | ((u32)l[3] << 16);
            size_t idx = (size_t)gidx * 32 + c4;
            wh[idx] = uh; wl[idx] = ul;
        }
    }
}

// ---------------- K3: QKV GEMM via mma.sync bf16 split (hi+lo) --------------
// grid (48, 12), 256 threads, warp grid 2(M) x 4(N), warp tile 64x32.
// D = Ahi*Bhi + Ahi*Blo + Alo*Bhi, fp32 accum.
// smem: bias[128] + 4 pitched bf16 tiles [128][136] (272B rows, ldmatrix-friendly)
#define KPB 136               // bf16 elements per smem row
#define ROWB 272              // bytes per smem row
#define TILEB (128 * ROWB)    // 34,816 B per tile
__global__ void __launch_bounds__(256, 1)
k_qkv(const float* __restrict__ bq, const float* __restrict__ bk,
      const float* __restrict__ bv) {
    extern __shared__ char smc[];
    float* bias_s = (float*)smc;          // 512 B
    char* aH = smc + 512;
    char* aL = aH + TILEB;
    char* bH = aL + TILEB;
    char* bL = bH + TILEB;

    int tid = threadIdx.x;
    int m0 = blockIdx.x * 128;
    int oc = blockIdx.y * 128;
    int mat = oc >> 9, o0 = oc & 511;
    const float* bias = mat == 0 ? bq : (mat == 1 ? bk : bv);
    if (tid < 128) bias_s[tid] = bias[o0 + tid];

    const uint2* xh = (const uint2*)g_xhi;
    const uint2* xl = (const uint2*)g_xlo;
    const uint2* wh = (const uint2*)g_whi;
    const uint2* wl = (const uint2*)g_wlo;

    for (int i = tid; i < 4096; i += 256) {
        int row = i >> 5, c4 = i & 31;
        int so = row * ROWB + c4 * 8;
        size_t ax = (size_t)(m0 + row) * 32 + c4;
        size_t bx = (size_t)(oc + row) * 32 + c4;
        *(uint2*)(aH + so) = xh[ax];
        *(uint2*)(aL + so) = xl[ax];
        *(uint2*)(bH + so) = wh[bx];
        *(uint2*)(bL + so) = wl[bx];
    }
    __syncthreads();

    u32 sb = smem_u32(smc);
    u32 aHb = sb + 512, aLb = aHb + TILEB, bHb = aLb + TILEB, bLb = bHb + TILEB;

    int t   = tid & 31;
    int wid = tid >> 5;
    int wm = (wid & 1) * 64;              // warp M offset
    int wn = (wid >> 1) * 32;             // warp N offset
    int rowA = ((t >> 3) & 1) * 8 + (t & 7);
    int kofA = (t >> 4) * 8;
    int rowB = (t & 7);
    int kofB = ((t >> 3) & 1) * 8;

    float acc[4][4][4];
    #pragma unroll
    for (int mf = 0; mf < 4; mf++)
        #pragma unroll
        for (int nf = 0; nf < 4; nf++)
            #pragma unroll
            for (int j = 0; j < 4; j++) acc[mf][nf][j] = 0.f;

    for (int k = 0; k < 128; k += 16) {
        u32 ah[4][4], al[4][4], bh[4][2], bl[4][2];
        #pragma unroll
        for (int mf = 0; mf < 4; mf++) {
            u32 off = (u32)((wm + mf * 16 + rowA) * ROWB + (k + kofA) * 2);
            ldsm_x4(ah[mf][0], ah[mf][1], ah[mf][2], ah[mf][3], aHb + off);
            ldsm_x4(al[mf][0], al[mf][1], al[mf][2], al[mf][3], aLb + off);
        }
        #pragma unroll
        for (int nf = 0; nf < 4; nf++) {
            u32 off = (u32)((wn + nf * 8 + rowB) * ROWB + (k + kofB) * 2);
            ldsm_x2(bh[nf][0], bh[nf][1], bHb + off);
            ldsm_x2(bl[nf][0], bl[nf][1], bLb + off);
        }
        #pragma unroll
        for (int mf = 0; mf < 4; mf++)
            #pragma unroll
            for (int nf = 0; nf < 4; nf++) {
                mma_bf16(acc[mf][nf], ah[mf], bh[nf]);
                mma_bf16(acc[mf][nf], ah[mf], bl[nf]);
                mma_bf16(acc[mf][nf], al[mf], bh[nf]);
            }
    }

    // epilogue: d0,d1 -> (row tq, cols 2tr..2tr+1); d2,d3 -> row tq+8
    int tq = t >> 2, tr = t & 3;
    #pragma unroll
    for (int mf = 0; mf < 4; mf++) {
        int m = m0 + wm + mf * 16 + tq;
        #pragma unroll
        for (int nf = 0; nf < 4; nf++) {
            int ln = wn + nf * 8 + tr * 2;
            float b0 = bias_s[ln], b1 = bias_s[ln + 1];
            float2 v0 = make_float2(acc[mf][nf][0] + b0, acc[mf][nf][1] + b1);
            float2 v1 = make_float2(acc[mf][nf][2] + b0, acc[mf][nf][3] + b1);
            *(float2*)(g_qkv + (size_t)m * QKV_W + oc + ln) = v0;
            *(float2*)(g_qkv + (size_t)(m + 8) * QKV_W + oc + ln) = v1;
        }
    }
}

// ---------------- K4: per-(set,head) attention -> g_part --------------------
__global__ void __launch_bounds__(192)
k_attn() {
    __shared__ float4 q4h[24 * 17];
    __shared__ float4 kt4[16 * 25];
    __shared__ float4 v4h[24 * 16];
    __shared__ float  alpha[24 * 24];

    int tid = threadIdx.x;
    int set = blockIdx.x >> 3;
    int h   = blockIdx.x & 7;
    int n0  = set * G;

    const float4* src4 = (const float4*)g_qkv + (size_t)n0 * 384;
    #pragma unroll
    for (int i = tid; i < 24 * 16; i += 192) {
        int n = i >> 4, c4 = i & 15;
        q4h[n * 17 + c4] = src4[n * 384 + h * 16 + c4];
        v4h[n * 16 + c4] = src4[n * 384 + 256 + h * 16 + c4];
        kt4[c4 * 25 + n] = src4[n * 384 + 128 + h * 16 + c4];
    }
    __syncthreads();

    {
        int d = tid >> 3, sg = tid & 7;
        float a0 = 0.f, a1 = 0.f, a2 = 0.f;
        #pragma unroll
        for (int j = 0; j < 16; j++) {
            float4 qq = q4h[d * 17 + j];
            const float4* kp = &kt4[j * 25 + sg * 3];
            float4 k0 = kp[0], k1 = kp[1], k2 = kp[2];
            a0 += qq.x * k0.x + qq.y * k0.y + qq.z * k0.z + qq.w * k0.w;
            a1 += qq.x * k1.x + qq.y * k1.y + qq.z * k1.z + qq.w * k1.w;
            a2 += qq.x * k2.x + qq.y * k2.y + qq.z * k2.z + qq.w * k2.w;
        }
        float* arow = alpha + d * G + sg * 3;
        arow[0] = a0 * 0.125f; arow[1] = a1 * 0.125f; arow[2] = a2 * 0.125f;
    }
    __syncthreads();

    if (tid < G) {
        float* row = alpha + tid * G;
        float m = row[0];
        #pragma unroll
        for (int s = 1; s < G; s++) m = fmaxf(m, row[s]);
        float e[G], sum = 0.f;
        #pragma unroll
        for (int s = 0; s < G; s++) { e[s] = expf(row[s] - m); sum += e[s]; }
        float inv = 1.0f / (sum + 1e-16f);
        #pragma unroll
        for (int s = 0; s < G; s++) row[s] = e[s] * inv;
    }
    __syncthreads();

    float4* part4 = (float4*)g_part;
    #pragma unroll
    for (int i = tid; i < G * 16; i += 192) {
        int d = i >> 4, c4 = i & 15;
        float4 acc = make_float4(0.f, 0.f, 0.f, 0.f);
        const float* ar = alpha + d * G;
        #pragma unroll
        for (int s = 0; s < G; s++) {
            float a = ar[s];
            float4 vv = v4h[s * 16 + c4];
            acc.x = fmaf(a, vv.x, acc.x);
            acc.y = fmaf(a, vv.y, acc.y);
            acc.z = fmaf(a, vv.z, acc.z);
            acc.w = fmaf(a, vv.w, acc.w);
        }
        acc.x *= 0.125f; acc.y *= 0.125f; acc.z *= 0.125f; acc.w *= 0.125f;
        part4[(size_t)(n0 + d) * 128 + h * 16 + c4] = acc;
    }
}

// ---------------- K5: sum heads + residual + h stats ------------------------
__global__ void __launch_bounds__(256)
k_hres(const float* __restrict__ x) {
    __shared__ float smS[16 * 64], smQ[16 * 64];
    int t  = threadIdx.x;
    int c4 = t & 15;
    int rs = t >> 4;
    int r0 = blockIdx.x * 128;

    const float4* part4 = (const float4*)g_part;
    const float4* xg    = (const float4*)x;
    float4* h4 = (float4*)g_h;

    float4 s = make_float4(0.f, 0.f, 0.f, 0.f);
    float4 q = make_float4(0.f, 0.f, 0.f, 0.f);
    #pragma unroll
    for (int r = rs; r < 128; r += 16) {
        size_t row = r0 + r;
        float4 a = make_float4(0.f, 0.f, 0.f, 0.f);
        #pragma unroll
        for (int hh = 0; hh < NH; hh++) {
            float4 p = part4[row * 128 + hh * 16 + c4];
            a.x += p.x; a.y += p.y; a.z += p.z; a.w += p.w;
        }
        float4 x0 = xg[row * 32 + c4];
        float4 x1 = xg[row * 32 + 16 + c4];
        a.x += x0.x + x1.x; a.y += x0.y + x1.y;
        a.z += x0.z + x1.z; a.w += x0.w + x1.w;
        h4[row * 16 + c4] = a;
        s.x += a.x; s.y += a.y; s.z += a.z; s.w += a.w;
        q.x += a.x * a.x; q.y += a.y * a.y; q.z += a.z * a.z; q.w += a.w * a.w;
    }
    ((float4*)smS)[rs * 16 + c4] = s;
    ((float4*)smQ)[rs * 16 + c4] = q;
    __syncthreads();
    if (t < 64) {
        float ss = 0.f, qq = 0.f;
        #pragma unroll
        for (int j = 0; j < 16; j++) { ss += smS[j * 64 + t]; qq += smQ[j * 64 + t]; }
        atomicAdd(&g_hsum[t], ss);
        atomicAdd(&g_hsumsq[t], qq);
    }
}

__device__ __forceinline__ float gelu_exact(float v) {
    return 0.5f * v * (1.0f + erff(v * 0.70710678118654752f));
}

// ---------------- K6: global norm + PFF + per-set norm + score + pooling ----
#define WP 65
__global__ void __launch_bounds__(256)
k_final(const float* __restrict__ x,
        const float* __restrict__ no_w, const float* __restrict__ no_b,
        const float* __restrict__ no_ms,
        const float* __restrict__ o_w1, const float* __restrict__ o_b1,
        const float* __restrict__ o_w2, const float* __restrict__ o_b2,
        const float* __restrict__ pn_w, const float* __restrict__ pn_b,
        const float* __restrict__ pn_ms,
        const float* __restrict__ p_w1, const float* __restrict__ p_b1,
        const float* __restrict__ p_w2, const float* __restrict__ p_b2,
        float* __restrict__ out) {
    extern __shared__ float dsm[];
    float* w1T  = dsm;
    float* w2T  = w1T + 64 * WP;
    float* pw1T = w2T + 64 * WP;
    float* hs   = pw1T + 64 * WP;
    float* hn   = hs + G * DH;
    float* t1   = hn + G * DH;
    float* h2   = t1 + G * DH;
    float* a2   = h2 + G * DH;
    float* b2   = a2 + DH;
    float* cm   = b2 + DH;
    float* cr   = cm + DH;
    float* b1s  = cr + DH;
    float* b2s  = b1s + DH;
    float* pb1s = b2s + DH;
    float* pw2s = pb1s + DH;
    float* score = pw2s + DH;
    float* wsf   = score + G;

    int tid = threadIdx.x;
    int n0  = blockIdx.x * G;

    for (int i = tid; i < 64 * 64; i += 256) {
        int j = i >> 6, c = i & 63;
        w1T[c * WP + j]  = o_w1[i];
        w2T[c * WP + j]  = o_w2[i];
        pw1T[c * WP + j] = p_w1[i];
    }
    if (tid < DH) {
        b1s[tid] = o_b1[tid]; b2s[tid] = o_b2[tid];
        pb1s[tid] = p_b1[tid]; pw2s[tid] = p_w2[tid];
        const float invN = 1.0f / NN;
        float mean = g_hsum[tid] * invN;
        float ex2  = g_hsumsq[tid] * invN;
        float mm   = mean * no_ms[tid];
        float var  = ex2 - 2.f * mm * mean + mm * mm;
        float rinv = rsqrtf(var + 1e-5f);
        a2[tid] = no_w[tid] * rinv;
        b2[tid] = no_b[tid] - no_w[tid] * rinv * mm;
    }
    for (int i = tid; i < G * DH; i += 256) hs[i] = g_h[(size_t)n0 * DH + i];
    __syncthreads();

    for (int i = tid; i < G * DH; i += 256) {
        int c = i & 63;
        hn[i] = fmaf(hs[i], a2[c], b2[c]);
    }
    __syncthreads();

    for (int i = tid; i < G * DH; i += 256) {
        int d = i >> 6, j = i & 63;
        float acc = b1s[j];
        const float* hr = hn + d * DH;
        #pragma unroll 16
        for (int c = 0; c < DH; c++) acc = fmaf(hr[c], w1T[c * WP + j], acc);
        t1[i] = gelu_exact(acc);
    }
    __syncthreads();

    for (int i = tid; i < G * DH; i += 256) {
        int d = i >> 6, c = i & 63;
        float acc = b2s[c];
        const float* tr = t1 + d * DH;
        #pragma unroll 16
        for (int j = 0; j < DH; j++) acc = fmaf(tr[j], w2T[j * WP + c], acc);
        h2[i] = hs[i] + acc;
    }
    __syncthreads();

    if (tid < DH) {
        int c = tid;
        float m = 0.f;
        #pragma unroll
        for (int d = 0; d < G; d++) m += h2[d * DH + c];
        m *= (1.0f / G);
        float mm = m * pn_ms[c];
        float vv = 0.f;
        #pragma unroll
        for (int d = 0; d < G; d++) { float t = h2[d * DH + c] - mm; vv += t * t; }
        vv *= (1.0f / G);
        cm[c] = mm;
        cr[c] = pn_w[c] * rsqrtf(vv + 1e-5f);
    }
    __syncthreads();

    for (int i = tid; i < G * DH; i += 256) {
        int c = i & 63;
        hn[i] = fmaf(h2[i] - cm[c], cr[c], pn_b[c]);
    }
    __syncthreads();

    for (int i = tid; i < G * DH; i += 256) {
        int d = i >> 6, j = i & 63;
        float acc = pb1s[j];
        const float* hr = hn + d * DH;
        #pragma unroll 16
        for (int c = 0; c < DH; c++) acc = fmaf(hr[c], pw1T[c * WP + j], acc);
        t1[i] = gelu_exact(acc);
    }
    __syncthreads();

    if (tid < G) {
        float acc = p_b2[0];
        const float* tr = t1 + tid * DH;
        #pragma unroll 16
        for (int j = 0; j < DH; j++) acc = fmaf(tr[j], pw2s[j], acc);
        score[tid] = acc;
    }
    __syncthreads();

    if (tid == 0) {
        float m = score[0];
        #pragma unroll
        for (int d = 1; d < G; d++) m = fmaxf(m, score[d]);
        float sum = 0.f;
        #pragma unroll
        for (int d = 0; d < G; d++) { wsf[d] = expf(score[d] - m); sum += wsf[d]; }
        float inv = 1.0f / (sum + 1e-16f);
        #pragma unroll
        for (int d = 0; d < G; d++) wsf[d] *= inv;
    }
    __syncthreads();

    if (tid < DIN) {
        float acc = 0.f;
        #pragma unroll
        for (int d = 0; d < G; d++)
            acc = fmaf(wsf[d], x[(size_t)(n0 + d) * DIN + tid], acc);
        out[blockIdx.x * DIN + tid] = acc;
    }
}

// ---------------- launch -----------------------------------------------------
extern "C" void kernel_launch(void* const* d_in, const int* in_sizes, int n_in,
                              void* d_out, int out_size) {
    const float* x     = (const float*)d_in[0];
    const float* nq_w  = (const float*)d_in[4];
    const float* nq_b  = (const float*)d_in[5];
    const float* nq_ms = (const float*)d_in[6];
    const float* wq    = (const float*)d_in[7];
    const float* bq    = (const float*)d_in[8];
    const float* wk    = (const float*)d_in[9];
    const float* bk    = (const float*)d_in[10];
    const float* wv    = (const float*)d_in[11];
    const float* bv    = (const float*)d_in[12];
    const float* no_w  = (const float*)d_in[13];
    const float* no_b  = (const float*)d_in[14];
    const float* no_ms = (const float*)d_in[15];
    const float* o_w1  = (const float*)d_in[16];
    const float* o_b1  = (const float*)d_in[17];
    const float* o_w2  = (const float*)d_in[18];
    const float* o_b2  = (const float*)d_in[19];
    const float* pn_w  = (const float*)d_in[20];
    const float* pn_b  = (const float*)d_in[21];
    const float* pn_ms = (const float*)d_in[22];
    const float* p_w1  = (const float*)d_in[23];
    const float* p_b1  = (const float*)d_in[24];
    const float* p_w2  = (const float*)d_in[25];
    const float* p_b2  = (const float*)d_in[26];
    float* out = (float*)d_out;

    const int smem_qkv = 512 + 4 * TILEB;                                    // 139,776 B
    const int smem_fin = (3 * 64 * WP + 4 * G * DH + 8 * DH + 2 * G) * 4;    // ~77 KB
    cudaFuncSetAttribute(k_qkv,   cudaFuncAttributeMaxDynamicSharedMemorySize, smem_qkv);
    cudaFuncSetAttribute(k_final, cudaFuncAttributeMaxDynamicSharedMemorySize, smem_fin);

    k_xstats<<<96, 256>>>(x);
    k_xnorm<<<60, 256>>>(x, nq_w, nq_b, nq_ms, wq, wk, wv);
    k_qkv<<<dim3(48, 12), 256, smem_qkv>>>(bq, bk, bv);
    k_attn<<<2048, 192>>>();
    k_hres<<<48, 256>>>(x);
    k_final<<<256, 256, smem_fin>>>(x, no_w, no_b, no_ms,
                                    o_w1, o_b1, o_w2, o_b2,
                                    pn_w, pn_b, pn_ms,
                                    p_w1, p_b1, p_w2, p_b2, out);
}

// round 6
// speedup vs baseline: 5.1974x; 1.1851x over previous
#include <cuda_runtime.h>
#include <cuda_bf16.h>
#include <math.h>
#include <string.h>

#define NN   6144
#define G    24
#define DIN  128
#define EFF  512
#define DH   64
#define NH   8
#define QKV_W 1536

typedef unsigned long long u64;
typedef unsigned int u32;

// ---------------- device scratch --------------------------------------------
__device__ float g_qkv[NN * QKV_W];            // 37.7 MB fp32 qkv
__device__ float g_part[NN * EFF];             // per-head attention partials
__device__ float g_h[NN * DH];
__device__ unsigned short g_xhi[NN * DIN];     // normalized x, bf16 hi
__device__ unsigned short g_xlo[NN * DIN];     // bf16 lo (residual)
__device__ unsigned short g_whi[QKV_W * DIN];  // weights q|k|v bf16 hi
__device__ unsigned short g_wlo[QKV_W * DIN];
__device__ float g_xs_part[96 * DIN];
__device__ float g_xq_part[96 * DIN];
__device__ float g_hsum[DH];
__device__ float g_hsumsq[DH];

// ---------------- PTX helpers (arch-agnostic: ldmatrix + mma.sync) ----------
__device__ __forceinline__ u32 smem_u32(const void* p) {
    u32 a;
    asm("{ .reg .u64 t; cvta.to.shared.u64 t, %1; cvt.u32.u64 %0, t; }"
        : "=r"(a) : "l"(p));
    return a;
}
__device__ __forceinline__ void ldsm_x4(u32& r0, u32& r1, u32& r2, u32& r3, u32 addr) {
    asm volatile("ldmatrix.sync.aligned.m8n8.x4.shared.b16 {%0,%1,%2,%3}, [%4];"
                 : "=r"(r0), "=r"(r1), "=r"(r2), "=r"(r3) : "r"(addr));
}
__device__ __forceinline__ void ldsm_x2(u32& r0, u32& r1, u32 addr) {
    asm volatile("ldmatrix.sync.aligned.m8n8.x2.shared.b16 {%0,%1}, [%2];"
                 : "=r"(r0), "=r"(r1) : "r"(addr));
}
__device__ __forceinline__ void mma_bf16(float* d, const u32* a, const u32* b) {
    asm volatile(
        "mma.sync.aligned.m16n8k16.row.col.f32.bf16.bf16.f32 "
        "{%0,%1,%2,%3},{%4,%5,%6,%7},{%8,%9},{%0,%1,%2,%3};"
        : "+f"(d[0]), "+f"(d[1]), "+f"(d[2]), "+f"(d[3])
        : "r"(a[0]), "r"(a[1]), "r"(a[2]), "r"(a[3]), "r"(b[0]), "r"(b[1]));
}

__device__ __forceinline__ unsigned short bf16bits(float v) {
    __nv_bfloat16 b = __float2bfloat16(v);
    unsigned short s; memcpy(&s, &b, 2); return s;
}
__device__ __forceinline__ float bf16val(float v) {
    return __bfloat162float(__float2bfloat16(v));
}

// ---------------- K1: x stats partials (96 blocks x 64 rows) ----------------
__global__ void __launch_bounds__(256)
k_xstats(const float* __restrict__ x) {
    __shared__ float smS[8 * 128], smQ[8 * 128];
    int t  = threadIdx.x;
    int c4 = t & 31;
    int rs = t >> 5;
    int r0 = blockIdx.x * 64;

    const float4* xg = (const float4*)x;
    float4 s = make_float4(0.f, 0.f, 0.f, 0.f);
    float4 q = make_float4(0.f, 0.f, 0.f, 0.f);
    #pragma unroll
    for (int r = rs; r < 64; r += 8) {
        float4 v = xg[(size_t)(r0 + r) * 32 + c4];
        s.x += v.x; s.y += v.y; s.z += v.z; s.w += v.w;
        q.x += v.x * v.x; q.y += v.y * v.y; q.z += v.z * v.z; q.w += v.w * v.w;
    }
    ((float4*)smS)[rs * 32 + c4] = s;
    ((float4*)smQ)[rs * 32 + c4] = q;
    __syncthreads();
    if (t < 128) {
        float ss = 0.f, qq = 0.f;
        #pragma unroll
        for (int j = 0; j < 8; j++) { ss += smS[j * 128 + t]; qq += smQ[j * 128 + t]; }
        g_xs_part[blockIdx.x * 128 + t] = ss;
        g_xq_part[blockIdx.x * 128 + t] = qq;
    }
}

// ---------------- K2: normalize x -> bf16 hi/lo; convert W -> bf16 hi/lo ----
__global__ void __launch_bounds__(256)
k_xnorm(const float* __restrict__ x,
        const float* __restrict__ nq_w, const float* __restrict__ nq_b,
        const float* __restrict__ nq_ms,
        const float* __restrict__ wq, const float* __restrict__ wk,
        const float* __restrict__ wv) {
    int tid = threadIdx.x;
    int b   = blockIdx.x;

    if (b == 0 && tid < DH) { g_hsum[tid] = 0.f; g_hsumsq[tid] = 0.f; }

    uint2* xh = (uint2*)g_xhi;
    uint2* xl = (uint2*)g_xlo;
    uint2* wh = (uint2*)g_whi;
    uint2* wl = (uint2*)g_wlo;

    if (b < 48) {
        __shared__ float As[128], Bs[128];
        if (tid < 128) {
            float ss = 0.f, qq = 0.f;
            #pragma unroll 8
            for (int p = 0; p < 96; p++) {
                ss += g_xs_part[p * 128 + tid];
                qq += g_xq_part[p * 128 + tid];
            }
            const float invN = 1.0f / NN;
            float mean = ss * invN;
            float ex2  = qq * invN;
            float mm   = mean * nq_ms[tid];
            float var  = ex2 - 2.f * mm * mean + mm * mm;
            float rinv = rsqrtf(var + 1e-5f);
            As[tid] = nq_w[tid] * rinv;
            Bs[tid] = nq_b[tid] - nq_w[tid] * rinv * mm;
        }
        __syncthreads();
        int r0 = b * 128;
        const float4* xg = (const float4*)x;
        for (int i = tid; i < 128 * 32; i += 256) {
            int row = i >> 5, c4 = i & 31, c = c4 * 4;
            float4 v = xg[(size_t)(r0 + row) * 32 + c4];
            float f[4];
            f[0] = fmaf(v.x, As[c],     Bs[c]);
            f[1] = fmaf(v.y, As[c + 1], Bs[c + 1]);
            f[2] = fmaf(v.z, As[c + 2], Bs[c + 2]);
            f[3] = fmaf(v.w, As[c + 3], Bs[c + 3]);
            unsigned short h[4], l[4];
            #pragma unroll
            for (int j = 0; j < 4; j++) {
                h[j] = bf16bits(f[j]);
                l[j] = bf16bits(f[j] - bf16val(f[j]));
            }
            uint2 uh, ul;
            uh.x = (u32)h[0] | ((u32)h[1] << 16); uh.y = (u32)h[2] | ((u32)h[3] << 16);
            ul.x = (u32)l[0] | ((u32)l[1] << 16); ul.y = (u32)l[2] | ((u32)l[3] << 16);
            size_t idx = (size_t)(r0 + row) * 32 + c4;
            xh[idx] = uh; xl[idx] = ul;
        }
    } else {
        int wr0 = (b - 48) * 128;
        for (int i = tid; i < 128 * 32; i += 256) {
            int row = i >> 5, c4 = i & 31;
            int gidx = wr0 + row;
            int mat = gidx >> 9, lr = gidx & 511;
            const float4* src = (const float4*)(mat == 0 ? wq : (mat == 1 ? wk : wv));
            float4 v = src[(size_t)lr * 32 + c4];
            float f[4] = {v.x, v.y, v.z, v.w};
            unsigned short h[4], l[4];
            #pragma unroll
            for (int j = 0; j < 4; j++) {
                h[j] = bf16bits(f[j]);
                l[j] = bf16bits(f[j] - bf16val(f[j]));
            }
            uint2 uh, ul;
            uh.x = (u32)h[0] | ((u32)h[1] << 16); uh.y = (u32)h[2] | ((u32)h[3] << 16);
            ul.x = (u32)l[0] | ((u32)l[1] << 16); ul.y = (u32)l[2] | ((u32)l[3] << 16);
            size_t idx = (size_t)gidx * 32 + c4;
            wh[idx] = uh; wl[idx] = ul;
        }
    }
}

// ---------------- K3: QKV GEMM via mma.sync bf16 split (hi+lo) --------------
// grid (48, 24), 256 threads, warp grid 4(M) x 2(N), warp tile 32x32.
// Tile M=128, N=64, K=128. smem ~105KB -> 2 CTAs/SM (phase overlap).
#define ROWB 272              // bytes per smem row (136 bf16, ldmatrix-friendly)
#define ATILE (128 * ROWB)    // 34,816 B
#define BTILE (64 * ROWB)     // 17,408 B
__global__ void __launch_bounds__(256, 2)
k_qkv(const float* __restrict__ bq, const float* __restrict__ bk,
      const float* __restrict__ bv) {
    extern __shared__ char smc[];
    float* bias_s = (float*)smc;          // 512 B (64 used)
    char* aH = smc + 512;
    char* aL = aH + ATILE;
    char* bH = aL + ATILE;
    char* bL = bH + BTILE;

    int tid = threadIdx.x;
    int m0 = blockIdx.x * 128;
    int oc = blockIdx.y * 64;
    int mat = oc >> 9, o0 = oc & 511;
    const float* bias = mat == 0 ? bq : (mat == 1 ? bk : bv);
    if (tid < 64) bias_s[tid] = bias[o0 + tid];

    const uint2* xh = (const uint2*)g_xhi;
    const uint2* xl = (const uint2*)g_xlo;
    const uint2* wh = (const uint2*)g_whi;
    const uint2* wl = (const uint2*)g_wlo;

    #pragma unroll
    for (int i = tid; i < 4096; i += 256) {
        int row = i >> 5, c4 = i & 31;
        int so = row * ROWB + c4 * 8;
        size_t ax = (size_t)(m0 + row) * 32 + c4;
        *(uint2*)(aH + so) = xh[ax];
        *(uint2*)(aL + so) = xl[ax];
    }
    #pragma unroll
    for (int i = tid; i < 2048; i += 256) {
        int row = i >> 5, c4 = i & 31;
        int so = row * ROWB + c4 * 8;
        size_t bx = (size_t)(oc + row) * 32 + c4;
        *(uint2*)(bH + so) = wh[bx];
        *(uint2*)(bL + so) = wl[bx];
    }
    __syncthreads();

    u32 sb = smem_u32(smc);
    u32 aHb = sb + 512, aLb = aHb + ATILE, bHb = aLb + ATILE, bLb = bHb + BTILE;

    int t   = tid & 31;
    int wid = tid >> 5;
    int wm = (wid & 3) * 32;              // warp M offset (4 warps)
    int wn = (wid >> 2) * 32;             // warp N offset (2 warps)
    int rowA = ((t >> 3) & 1) * 8 + (t & 7);
    int kofA = (t >> 4) * 8;
    int rowB = (t & 7);
    int kofB = ((t >> 3) & 1) * 8;

    float acc[2][4][4];
    #pragma unroll
    for (int mf = 0; mf < 2; mf++)
        #pragma unroll
        for (int nf = 0; nf < 4; nf++)
            #pragma unroll
            for (int j = 0; j < 4; j++) acc[mf][nf][j] = 0.f;

    for (int k = 0; k < 128; k += 16) {
        u32 ah[2][4], al[2][4], bh[4][2], bl[4][2];
        #pragma unroll
        for (int mf = 0; mf < 2; mf++) {
            u32 off = (u32)((wm + mf * 16 + rowA) * ROWB + (k + kofA) * 2);
            ldsm_x4(ah[mf][0], ah[mf][1], ah[mf][2], ah[mf][3], aHb + off);
            ldsm_x4(al[mf][0], al[mf][1], al[mf][2], al[mf][3], aLb + off);
        }
        #pragma unroll
        for (int nf = 0; nf < 4; nf++) {
            u32 off = (u32)((wn + nf * 8 + rowB) * ROWB + (k + kofB) * 2);
            ldsm_x2(bh[nf][0], bh[nf][1], bHb + off);
            ldsm_x2(bl[nf][0], bl[nf][1], bLb + off);
        }
        #pragma unroll
        for (int mf = 0; mf < 2; mf++)
            #pragma unroll
            for (int nf = 0; nf < 4; nf++) {
                mma_bf16(acc[mf][nf], ah[mf], bh[nf]);
                mma_bf16(acc[mf][nf], ah[mf], bl[nf]);
                mma_bf16(acc[mf][nf], al[mf], bh[nf]);
            }
    }

    int tq = t >> 2, tr = t & 3;
    #pragma unroll
    for (int mf = 0; mf < 2; mf++) {
        int m = m0 + wm + mf * 16 + tq;
        #pragma unroll
        for (int nf = 0; nf < 4; nf++) {
            int ln = wn + nf * 8 + tr * 2;
            float b0 = bias_s[ln], b1 = bias_s[ln + 1];
            float2 v0 = make_float2(acc[mf][nf][0] + b0, acc[mf][nf][1] + b1);
            float2 v1 = make_float2(acc[mf][nf][2] + b0, acc[mf][nf][3] + b1);
            *(float2*)(g_qkv + (size_t)m * QKV_W + oc + ln) = v0;
            *(float2*)(g_qkv + (size_t)(m + 8) * QKV_W + oc + ln) = v1;
        }
    }
}

// ---------------- K4: per-(set,head) attention -> g_part --------------------
// 8 CTAs/SM target: reg-lean softmax (no e[] array), 192 threads
__global__ void __launch_bounds__(192, 8)
k_attn() {
    __shared__ float4 q4h[24 * 17];
    __shared__ float4 kt4[16 * 25];
    __shared__ float4 v4h[24 * 16];
    __shared__ float  alpha[24 * 24];

    int tid = threadIdx.x;
    int set = blockIdx.x >> 3;
    int h   = blockIdx.x & 7;
    int n0  = set * G;

    const float4* src4 = (const float4*)g_qkv + (size_t)n0 * 384;
    #pragma unroll
    for (int i = tid; i < 24 * 16; i += 192) {
        int n = i >> 4, c4 = i & 15;
        q4h[n * 17 + c4] = src4[n * 384 + h * 16 + c4];
        v4h[n * 16 + c4] = src4[n * 384 + 256 + h * 16 + c4];
        kt4[c4 * 25 + n] = src4[n * 384 + 128 + h * 16 + c4];
    }
    __syncthreads();

    {
        int d = tid >> 3, sg = tid & 7;
        float a0 = 0.f, a1 = 0.f, a2 = 0.f;
        #pragma unroll
        for (int j = 0; j < 16; j++) {
            float4 qq = q4h[d * 17 + j];
            const float4* kp = &kt4[j * 25 + sg * 3];
            float4 k0 = kp[0], k1 = kp[1], k2 = kp[2];
            a0 += qq.x * k0.x + qq.y * k0.y + qq.z * k0.z + qq.w * k0.w;
            a1 += qq.x * k1.x + qq.y * k1.y + qq.z * k1.z + qq.w * k1.w;
            a2 += qq.x * k2.x + qq.y * k2.y + qq.z * k2.z + qq.w * k2.w;
        }
        float* arow = alpha + d * G + sg * 3;
        arow[0] = a0 * 0.125f; arow[1] = a1 * 0.125f; arow[2] = a2 * 0.125f;
    }
    __syncthreads();

    // softmax per destination d, in-place in smem (no register array)
    if (tid < G) {
        float* row = alpha + tid * G;
        float m = row[0];
        #pragma unroll
        for (int s = 1; s < G; s++) m = fmaxf(m, row[s]);
        float sum = 0.f;
        #pragma unroll
        for (int s = 0; s < G; s++) {
            float e = expf(row[s] - m);
            row[s] = e;
            sum += e;
        }
        float inv = 1.0f / (sum + 1e-16f);
        #pragma unroll
        for (int s = 0; s < G; s++) row[s] *= inv;
    }
    __syncthreads();

    float4* part4 = (float4*)g_part;
    #pragma unroll
    for (int i = tid; i < G * 16; i += 192) {
        int d = i >> 4, c4 = i & 15;
        float4 acc = make_float4(0.f, 0.f, 0.f, 0.f);
        const float* ar = alpha + d * G;
        #pragma unroll
        for (int s = 0; s < G; s++) {
            float a = ar[s];
            float4 vv = v4h[s * 16 + c4];
            acc.x = fmaf(a, vv.x, acc.x);
            acc.y = fmaf(a, vv.y, acc.y);
            acc.z = fmaf(a, vv.z, acc.z);
            acc.w = fmaf(a, vv.w, acc.w);
        }
        acc.x *= 0.125f; acc.y *= 0.125f; acc.z *= 0.125f; acc.w *= 0.125f;
        part4[(size_t)(n0 + d) * 128 + h * 16 + c4] = acc;
    }
}

// ---------------- K5: sum heads + residual + h stats ------------------------
__global__ void __launch_bounds__(256)
k_hres(const float* __restrict__ x) {
    __shared__ float smS[16 * 64], smQ[16 * 64];
    int t  = threadIdx.x;
    int c4 = t & 15;
    int rs = t >> 4;
    int r0 = blockIdx.x * 128;

    const float4* part4 = (const float4*)g_part;
    const float4* xg    = (const float4*)x;
    float4* h4 = (float4*)g_h;

    float4 s = make_float4(0.f, 0.f, 0.f, 0.f);
    float4 q = make_float4(0.f, 0.f, 0.f, 0.f);
    #pragma unroll
    for (int r = rs; r < 128; r += 16) {
        size_t row = r0 + r;
        float4 a = make_float4(0.f, 0.f, 0.f, 0.f);
        #pragma unroll
        for (int hh = 0; hh < NH; hh++) {
            float4 p = part4[row * 128 + hh * 16 + c4];
            a.x += p.x; a.y += p.y; a.z += p.z; a.w += p.w;
        }
        float4 x0 = xg[row * 32 + c4];
        float4 x1 = xg[row * 32 + 16 + c4];
        a.x += x0.x + x1.x; a.y += x0.y + x1.y;
        a.z += x0.z + x1.z; a.w += x0.w + x1.w;
        h4[row * 16 + c4] = a;
        s.x += a.x; s.y += a.y; s.z += a.z; s.w += a.w;
        q.x += a.x * a.x; q.y += a.y * a.y; q.z += a.z * a.z; q.w += a.w * a.w;
    }
    ((float4*)smS)[rs * 16 + c4] = s;
    ((float4*)smQ)[rs * 16 + c4] = q;
    __syncthreads();
    if (t < 64) {
        float ss = 0.f, qq = 0.f;
        #pragma unroll
        for (int j = 0; j < 16; j++) { ss += smS[j * 64 + t]; qq += smQ[j * 64 + t]; }
        atomicAdd(&g_hsum[t], ss);
        atomicAdd(&g_hsumsq[t], qq);
    }
}

__device__ __forceinline__ float gelu_exact(float v) {
    return 0.5f * v * (1.0f + erff(v * 0.70710678118654752f));
}

// ---------------- K6: global norm + PFF + per-set norm + score + pooling ----
#define WP 65
__global__ void __launch_bounds__(256)
k_final(const float* __restrict__ x,
        const float* __restrict__ no_w, const float* __restrict__ no_b,
        const float* __restrict__ no_ms,
        const float* __restrict__ o_w1, const float* __restrict__ o_b1,
        const float* __restrict__ o_w2, const float* __restrict__ o_b2,
        const float* __restrict__ pn_w, const float* __restrict__ pn_b,
        const float* __restrict__ pn_ms,
        const float* __restrict__ p_w1, const float* __restrict__ p_b1,
        const float* __restrict__ p_w2, const float* __restrict__ p_b2,
        float* __restrict__ out) {
    extern __shared__ float dsm[];
    float* w1T  = dsm;
    float* w2T  = w1T + 64 * WP;
    float* pw1T = w2T + 64 * WP;
    float* hs   = pw1T + 64 * WP;
    float* hn   = hs + G * DH;
    float* t1   = hn + G * DH;
    float* h2   = t1 + G * DH;
    float* a2   = h2 + G * DH;
    float* b2   = a2 + DH;
    float* cm   = b2 + DH;
    float* cr   = cm + DH;
    float* b1s  = cr + DH;
    float* b2s  = b1s + DH;
    float* pb1s = b2s + DH;
    float* pw2s = pb1s + DH;
    float* score = pw2s + DH;
    float* wsf   = score + G;

    int tid = threadIdx.x;
    int n0  = blockIdx.x * G;

    for (int i = tid; i < 64 * 64; i += 256) {
        int j = i >> 6, c = i & 63;
        w1T[c * WP + j]  = o_w1[i];
        w2T[c * WP + j]  = o_w2[i];
        pw1T[c * WP + j] = p_w1[i];
    }
    if (tid < DH) {
        b1s[tid] = o_b1[tid]; b2s[tid] = o_b2[tid];
        pb1s[tid] = p_b1[tid]; pw2s[tid] = p_w2[tid];
        const float invN = 1.0f / NN;
        float mean = g_hsum[tid] * invN;
        float ex2  = g_hsumsq[tid] * invN;
        float mm   = mean * no_ms[tid];
        float var  = ex2 - 2.f * mm * mean + mm * mm;
        float rinv = rsqrtf(var + 1e-5f);
        a2[tid] = no_w[tid] * rinv;
        b2[tid] = no_b[tid] - no_w[tid] * rinv * mm;
    }
    for (int i = tid; i < G * DH; i += 256) hs[i] = g_h[(size_t)n0 * DH + i];
    __syncthreads();

    for (int i = tid; i < G * DH; i += 256) {
        int c = i & 63;
        hn[i] = fmaf(hs[i], a2[c], b2[c]);
    }
    __syncthreads();

    for (int i = tid; i < G * DH; i += 256) {
        int d = i >> 6, j = i & 63;
        float acc = b1s[j];
        const float* hr = hn + d * DH;
        #pragma unroll 16
        for (int c = 0; c < DH; c++) acc = fmaf(hr[c], w1T[c * WP + j], acc);
        t1[i] = gelu_exact(acc);
    }
    __syncthreads();

    for (int i = tid; i < G * DH; i += 256) {
        int d = i >> 6, c = i & 63;
        float acc = b2s[c];
        const float* tr = t1 + d * DH;
        #pragma unroll 16
        for (int j = 0; j < DH; j++) acc = fmaf(tr[j], w2T[j * WP + c], acc);
        h2[i] = hs[i] + acc;
    }
    __syncthreads();

    if (tid < DH) {
        int c = tid;
        float m = 0.f;
        #pragma unroll
        for (int d = 0; d < G; d++) m += h2[d * DH + c];
        m *= (1.0f / G);
        float mm = m * pn_ms[c];
        float vv = 0.f;
        #pragma unroll
        for (int d = 0; d < G; d++) { float t = h2[d * DH + c] - mm; vv += t * t; }
        vv *= (1.0f / G);
        cm[c] = mm;
        cr[c] = pn_w[c] * rsqrtf(vv + 1e-5f);
    }
    __syncthreads();

    for (int i = tid; i < G * DH; i += 256) {
        int c = i & 63;
        hn[i] = fmaf(h2[i] - cm[c], cr[c], pn_b[c]);
    }
    __syncthreads();

    for (int i = tid; i < G * DH; i += 256) {
        int d = i >> 6, j = i & 63;
        float acc = pb1s[j];
        const float* hr = hn + d * DH;
        #pragma unroll 16
        for (int c = 0; c < DH; c++) acc = fmaf(hr[c], pw1T[c * WP + j], acc);
        t1[i] = gelu_exact(acc);
    }
    __syncthreads();

    if (tid < G) {
        float acc = p_b2[0];
        const float* tr = t1 + tid * DH;
        #pragma unroll 16
        for (int j = 0; j < DH; j++) acc = fmaf(tr[j], pw2s[j], acc);
        score[tid] = acc;
    }
    __syncthreads();

    if (tid == 0) {
        float m = score[0];
        #pragma unroll
        for (int d = 1; d < G; d++) m = fmaxf(m, score[d]);
        float sum = 0.f;
        #pragma unroll
        for (int d = 0; d < G; d++) { wsf[d] = expf(score[d] - m); sum += wsf[d]; }
        float inv = 1.0f / (sum + 1e-16f);
        #pragma unroll
        for (int d = 0; d < G; d++) wsf[d] *= inv;
    }
    __syncthreads();

    if (tid < DIN) {
        float acc = 0.f;
        #pragma unroll
        for (int d = 0; d < G; d++)
            acc = fmaf(wsf[d], x[(size_t)(n0 + d) * DIN + tid], acc);
        out[blockIdx.x * DIN + tid] = acc;
    }
}

// ---------------- launch -----------------------------------------------------
extern "C" void kernel_launch(void* const* d_in, const int* in_sizes, int n_in,
                              void* d_out, int out_size) {
    const float* x     = (const float*)d_in[0];
    const float* nq_w  = (const float*)d_in[4];
    const float* nq_b  = (const float*)d_in[5];
    const float* nq_ms = (const float*)d_in[6];
    const float* wq    = (const float*)d_in[7];
    const float* bq    = (const float*)d_in[8];
    const float* wk    = (const float*)d_in[9];
    const float* bk    = (const float*)d_in[10];
    const float* wv    = (const float*)d_in[11];
    const float* bv    = (const float*)d_in[12];
    const float* no_w  = (const float*)d_in[13];
    const float* no_b  = (const float*)d_in[14];
    const float* no_ms = (const float*)d_in[15];
    const float* o_w1  = (const float*)d_in[16];
    const float* o_b1  = (const float*)d_in[17];
    const float* o_w2  = (const float*)d_in[18];
    const float* o_b2  = (const float*)d_in[19];
    const float* pn_w  = (const float*)d_in[20];
    const float* pn_b  = (const float*)d_in[21];
    const float* pn_ms = (const float*)d_in[22];
    const float* p_w1  = (const float*)d_in[23];
    const float* p_b1  = (const float*)d_in[24];
    const float* p_w2  = (const float*)d_in[25];
    const float* p_b2  = (const float*)d_in[26];
    float* out = (float*)d_out;

    const int smem_qkv = 512 + 2 * ATILE + 2 * BTILE;                        // 104,960 B
    const int smem_fin = (3 * 64 * WP + 4 * G * DH + 8 * DH + 2 * G) * 4;    // ~77 KB
    cudaFuncSetAttribute(k_qkv,   cudaFuncAttributeMaxDynamicSharedMemorySize, smem_qkv);
    cudaFuncSetAttribute(k_final, cudaFuncAttributeMaxDynamicSharedMemorySize, smem_fin);

    k_xstats<<<96, 256>>>(x);
    k_xnorm<<<60, 256>>>(x, nq_w, nq_b, nq_ms, wq, wk, wv);
    k_qkv<<<dim3(48, 24), 256, smem_qkv>>>(bq, bk, bv);
    k_attn<<<2048, 192>>>();
    k_hres<<<48, 256>>>(x);
    k_final<<<256, 256, smem_fin>>>(x, no_w, no_b, no_ms,
                                    o_w1, o_b1, o_w2, o_b2,
                                    pn_w, pn_b, pn_ms,
                                    p_w1, p_b1, p_w2, p_b2, out);
}

// round 7
// speedup vs baseline: 5.5242x; 1.0629x over previous
#include <cuda_runtime.h>
#include <cuda_bf16.h>
#include <math.h>
#include <string.h>

#define NN   6144
#define G    24
#define DIN  128
#define EFF  512
#define DH   64
#define NH   8
#define QKV_W 1536

typedef unsigned long long u64;
typedef unsigned int u32;

// ---------------- device scratch --------------------------------------------
__device__ float g_qkv[NN * QKV_W];            // 37.7 MB fp32 qkv
__device__ float g_h[NN * DH];                 // residual-init + attn accum
__device__ unsigned short g_xhi[NN * DIN];
__device__ unsigned short g_xlo[NN * DIN];
__device__ unsigned short g_whi[QKV_W * DIN];
__device__ unsigned short g_wlo[QKV_W * DIN];
__device__ float g_xs_part[96 * DIN];
__device__ float g_xq_part[96 * DIN];
__device__ float g_hsum[DH];
__device__ float g_hsumsq[DH];

// ---------------- PTX helpers -----------------------------------------------
__device__ __forceinline__ u32 smem_u32(const void* p) {
    u32 a;
    asm("{ .reg .u64 t; cvta.to.shared.u64 t, %1; cvt.u32.u64 %0, t; }"
        : "=r"(a) : "l"(p));
    return a;
}
__device__ __forceinline__ void ldsm_x4(u32& r0, u32& r1, u32& r2, u32& r3, u32 addr) {
    asm volatile("ldmatrix.sync.aligned.m8n8.x4.shared.b16 {%0,%1,%2,%3}, [%4];"
                 : "=r"(r0), "=r"(r1), "=r"(r2), "=r"(r3) : "r"(addr));
}
__device__ __forceinline__ void ldsm_x2(u32& r0, u32& r1, u32 addr) {
    asm volatile("ldmatrix.sync.aligned.m8n8.x2.shared.b16 {%0,%1}, [%2];"
                 : "=r"(r0), "=r"(r1) : "r"(addr));
}
__device__ __forceinline__ void mma_bf16(float* d, const u32* a, const u32* b) {
    asm volatile(
        "mma.sync.aligned.m16n8k16.row.col.f32.bf16.bf16.f32 "
        "{%0,%1,%2,%3},{%4,%5,%6,%7},{%8,%9},{%0,%1,%2,%3};"
        : "+f"(d[0]), "+f"(d[1]), "+f"(d[2]), "+f"(d[3])
        : "r"(a[0]), "r"(a[1]), "r"(a[2]), "r"(a[3]), "r"(b[0]), "r"(b[1]));
}

__device__ __forceinline__ unsigned short bf16bits(float v) {
    __nv_bfloat16 b = __float2bfloat16(v);
    unsigned short s; memcpy(&s, &b, 2); return s;
}
__device__ __forceinline__ float bf16val(float v) {
    return __bfloat162float(__float2bfloat16(v));
}

// ---------------- K1: x stats partials --------------------------------------
__global__ void __launch_bounds__(256)
k_xstats(const float* __restrict__ x) {
    __shared__ float smS[8 * 128], smQ[8 * 128];
    int t  = threadIdx.x;
    int c4 = t & 31;
    int rs = t >> 5;
    int r0 = blockIdx.x * 64;

    const float4* xg = (const float4*)x;
    float4 s = make_float4(0.f, 0.f, 0.f, 0.f);
    float4 q = make_float4(0.f, 0.f, 0.f, 0.f);
    #pragma unroll
    for (int r = rs; r < 64; r += 8) {
        float4 v = xg[(size_t)(r0 + r) * 32 + c4];
        s.x += v.x; s.y += v.y; s.z += v.z; s.w += v.w;
        q.x += v.x * v.x; q.y += v.y * v.y; q.z += v.z * v.z; q.w += v.w * v.w;
    }
    ((float4*)smS)[rs * 32 + c4] = s;
    ((float4*)smQ)[rs * 32 + c4] = q;
    __syncthreads();
    if (t < 128) {
        float ss = 0.f, qq = 0.f;
        #pragma unroll
        for (int j = 0; j < 8; j++) { ss += smS[j * 128 + t]; qq += smQ[j * 128 + t]; }
        g_xs_part[blockIdx.x * 128 + t] = ss;
        g_xq_part[blockIdx.x * 128 + t] = qq;
    }
}

// ---------------- K2: normalize x -> bf16 hi/lo; W -> bf16 hi/lo; h init ----
__global__ void __launch_bounds__(256)
k_xnorm(const float* __restrict__ x,
        const float* __restrict__ nq_w, const float* __restrict__ nq_b,
        const float* __restrict__ nq_ms,
        const float* __restrict__ wq, const float* __restrict__ wk,
        const float* __restrict__ wv) {
    int tid = threadIdx.x;
    int b   = blockIdx.x;

    if (b == 0 && tid < DH) { g_hsum[tid] = 0.f; g_hsumsq[tid] = 0.f; }

    uint2* xh = (uint2*)g_xhi;
    uint2* xl = (uint2*)g_xlo;
    uint2* wh = (uint2*)g_whi;
    uint2* wl = (uint2*)g_wlo;

    if (b < 48) {
        __shared__ float As[128], Bs[128];
        if (tid < 128) {
            float ss = 0.f, qq = 0.f;
            #pragma unroll 8
            for (int p = 0; p < 96; p++) {
                ss += g_xs_part[p * 128 + tid];
                qq += g_xq_part[p * 128 + tid];
            }
            const float invN = 1.0f / NN;
            float mean = ss * invN;
            float ex2  = qq * invN;
            float mm   = mean * nq_ms[tid];
            float var  = ex2 - 2.f * mm * mean + mm * mm;
            float rinv = rsqrtf(var + 1e-5f);
            As[tid] = nq_w[tid] * rinv;
            Bs[tid] = nq_b[tid] - nq_w[tid] * rinv * mm;
        }
        __syncthreads();
        int r0 = b * 128;
        const float4* xg = (const float4*)x;
        for (int i = tid; i < 128 * 32; i += 256) {
            int row = i >> 5, c4 = i & 31, c = c4 * 4;
            float4 v = xg[(size_t)(r0 + row) * 32 + c4];
            float f[4];
            f[0] = fmaf(v.x, As[c],     Bs[c]);
            f[1] = fmaf(v.y, As[c + 1], Bs[c + 1]);
            f[2] = fmaf(v.z, As[c + 2], Bs[c + 2]);
            f[3] = fmaf(v.w, As[c + 3], Bs[c + 3]);
            unsigned short h[4], l[4];
            #pragma unroll
            for (int j = 0; j < 4; j++) {
                h[j] = bf16bits(f[j]);
                l[j] = bf16bits(f[j] - bf16val(f[j]));
            }
            uint2 uh, ul;
            uh.x = (u32)h[0] | ((u32)h[1] << 16); uh.y = (u32)h[2] | ((u32)h[3] << 16);
            ul.x = (u32)l[0] | ((u32)l[1] << 16); ul.y = (u32)l[2] | ((u32)l[3] << 16);
            size_t idx = (size_t)(r0 + row) * 32 + c4;
            xh[idx] = uh; xl[idx] = ul;
        }
        // residual init: g_h = x[:, :64] + x[:, 64:]
        float4* h4 = (float4*)g_h;
        for (int i = tid; i < 128 * 16; i += 256) {
            int row = i >> 4, c4 = i & 15;
            float4 xa = xg[(size_t)(r0 + row) * 32 + c4];
            float4 xb = xg[(size_t)(r0 + row) * 32 + 16 + c4];
            h4[(size_t)(r0 + row) * 16 + c4] =
                make_float4(xa.x + xb.x, xa.y + xb.y, xa.z + xb.z, xa.w + xb.w);
        }
    } else {
        int wr0 = (b - 48) * 128;
        for (int i = tid; i < 128 * 32; i += 256) {
            int row = i >> 5, c4 = i & 31;
            int gidx = wr0 + row;
            int mat = gidx >> 9, lr = gidx & 511;
            const float4* src = (const float4*)(mat == 0 ? wq : (mat == 1 ? wk : wv));
            float4 v = src[(size_t)lr * 32 + c4];
            float f[4] = {v.x, v.y, v.z, v.w};
            unsigned short h[4], l[4];
            #pragma unroll
            for (int j = 0; j < 4; j++) {
                h[j] = bf16bits(f[j]);
                l[j] = bf16bits(f[j] - bf16val(f[j]));
            }
            uint2 uh, ul;
            uh.x = (u32)h[0] | ((u32)h[1] << 16); uh.y = (u32)h[2] | ((u32)h[3] << 16);
            ul.x = (u32)l[0] | ((u32)l[1] << 16); ul.y = (u32)l[2] | ((u32)l[3] << 16);
            size_t idx = (size_t)gidx * 32 + c4;
            wh[idx] = uh; wl[idx] = ul;
        }
    }
}

// ---------------- K3: QKV GEMM via mma.sync bf16 split (hi+lo) --------------
#define ROWB 272
#define ATILE (128 * ROWB)
#define BTILE (64 * ROWB)
__global__ void __launch_bounds__(256, 2)
k_qkv(const float* __restrict__ bq, const float* __restrict__ bk,
      const float* __restrict__ bv) {
    extern __shared__ char smc[];
    float* bias_s = (float*)smc;
    char* aH = smc + 512;
    char* aL = aH + ATILE;
    char* bH = aL + ATILE;
    char* bL = bH + BTILE;

    int tid = threadIdx.x;
    int m0 = blockIdx.x * 128;
    int oc = blockIdx.y * 64;
    int mat = oc >> 9, o0 = oc & 511;
    const float* bias = mat == 0 ? bq : (mat == 1 ? bk : bv);
    if (tid < 64) bias_s[tid] = bias[o0 + tid];

    const uint2* xh = (const uint2*)g_xhi;
    const uint2* xl = (const uint2*)g_xlo;
    const uint2* wh = (const uint2*)g_whi;
    const uint2* wl = (const uint2*)g_wlo;

    #pragma unroll
    for (int i = tid; i < 4096; i += 256) {
        int row = i >> 5, c4 = i & 31;
        int so = row * ROWB + c4 * 8;
        size_t ax = (size_t)(m0 + row) * 32 + c4;
        *(uint2*)(aH + so) = xh[ax];
        *(uint2*)(aL + so) = xl[ax];
    }
    #pragma unroll
    for (int i = tid; i < 2048; i += 256) {
        int row = i >> 5, c4 = i & 31;
        int so = row * ROWB + c4 * 8;
        size_t bx = (size_t)(oc + row) * 32 + c4;
        *(uint2*)(bH + so) = wh[bx];
        *(uint2*)(bL + so) = wl[bx];
    }
    __syncthreads();

    u32 sb = smem_u32(smc);
    u32 aHb = sb + 512, aLb = aHb + ATILE, bHb = aLb + ATILE, bLb = bHb + BTILE;

    int t   = tid & 31;
    int wid = tid >> 5;
    int wm = (wid & 3) * 32;
    int wn = (wid >> 2) * 32;
    int rowA = ((t >> 3) & 1) * 8 + (t & 7);
    int kofA = (t >> 4) * 8;
    int rowB = (t & 7);
    int kofB = ((t >> 3) & 1) * 8;

    float acc[2][4][4];
    #pragma unroll
    for (int mf = 0; mf < 2; mf++)
        #pragma unroll
        for (int nf = 0; nf < 4; nf++)
            #pragma unroll
            for (int j = 0; j < 4; j++) acc[mf][nf][j] = 0.f;

    for (int k = 0; k < 128; k += 16) {
        u32 ah[2][4], al[2][4], bh[4][2], bl[4][2];
        #pragma unroll
        for (int mf = 0; mf < 2; mf++) {
            u32 off = (u32)((wm + mf * 16 + rowA) * ROWB + (k + kofA) * 2);
            ldsm_x4(ah[mf][0], ah[mf][1], ah[mf][2], ah[mf][3], aHb + off);
            ldsm_x4(al[mf][0], al[mf][1], al[mf][2], al[mf][3], aLb + off);
        }
        #pragma unroll
        for (int nf = 0; nf < 4; nf++) {
            u32 off = (u32)((wn + nf * 8 + rowB) * ROWB + (k + kofB) * 2);
            ldsm_x2(bh[nf][0], bh[nf][1], bHb + off);
            ldsm_x2(bl[nf][0], bl[nf][1], bLb + off);
        }
        #pragma unroll
        for (int mf = 0; mf < 2; mf++)
            #pragma unroll
            for (int nf = 0; nf < 4; nf++) {
                mma_bf16(acc[mf][nf], ah[mf], bh[nf]);
                mma_bf16(acc[mf][nf], ah[mf], bl[nf]);
                mma_bf16(acc[mf][nf], al[mf], bh[nf]);
            }
    }

    int tq = t >> 2, tr = t & 3;
    #pragma unroll
    for (int mf = 0; mf < 2; mf++) {
        int m = m0 + wm + mf * 16 + tq;
        #pragma unroll
        for (int nf = 0; nf < 4; nf++) {
            int ln = wn + nf * 8 + tr * 2;
            float b0 = bias_s[ln], b1 = bias_s[ln + 1];
            float2 v0 = make_float2(acc[mf][nf][0] + b0, acc[mf][nf][1] + b1);
            float2 v1 = make_float2(acc[mf][nf][2] + b0, acc[mf][nf][3] + b1);
            *(float2*)(g_qkv + (size_t)m * QKV_W + oc + ln) = v0;
            *(float2*)(g_qkv + (size_t)(m + 8) * QKV_W + oc + ln) = v1;
        }
    }
}

// ---------------- K4: per-(set,head) attention -> atomicAdd into g_h --------
__global__ void __launch_bounds__(192, 8)
k_attn() {
    __shared__ float4 q4h[24 * 17];
    __shared__ float4 kt4[16 * 25];
    __shared__ float4 v4h[24 * 16];
    __shared__ float  alpha[24 * 24];

    int tid = threadIdx.x;
    int set = blockIdx.x >> 3;
    int h   = blockIdx.x & 7;
    int n0  = set * G;

    const float4* src4 = (const float4*)g_qkv + (size_t)n0 * 384;
    #pragma unroll
    for (int i = tid; i < 24 * 16; i += 192) {
        int n = i >> 4, c4 = i & 15;
        q4h[n * 17 + c4] = src4[n * 384 + h * 16 + c4];
        v4h[n * 16 + c4] = src4[n * 384 + 256 + h * 16 + c4];
        kt4[c4 * 25 + n] = src4[n * 384 + 128 + h * 16 + c4];
    }
    __syncthreads();

    // logits: 96 threads, each 2 d x 3 s (fewer total LDS wavefronts)
    if (tid < 96) {
        int d0 = (tid >> 3) * 2;
        int sg = tid & 7;
        float a00 = 0.f, a01 = 0.f, a02 = 0.f;
        float a10 = 0.f, a11 = 0.f, a12 = 0.f;
        #pragma unroll
        for (int j = 0; j < 16; j++) {
            float4 q0 = q4h[d0 * 17 + j];
            float4 q1 = q4h[(d0 + 1) * 17 + j];
            const float4* kp = &kt4[j * 25 + sg * 3];
            float4 k0 = kp[0], k1 = kp[1], k2 = kp[2];
            a00 += q0.x * k0.x + q0.y * k0.y + q0.z * k0.z + q0.w * k0.w;
            a01 += q0.x * k1.x + q0.y * k1.y + q0.z * k1.z + q0.w * k1.w;
            a02 += q0.x * k2.x + q0.y * k2.y + q0.z * k2.z + q0.w * k2.w;
            a10 += q1.x * k0.x + q1.y * k0.y + q1.z * k0.z + q1.w * k0.w;
            a11 += q1.x * k1.x + q1.y * k1.y + q1.z * k1.z + q1.w * k1.w;
            a12 += q1.x * k2.x + q1.y * k2.y + q1.z * k2.z + q1.w * k2.w;
        }
        float* r0 = alpha + d0 * G + sg * 3;
        float* r1 = r0 + G;
        r0[0] = a00 * 0.125f; r0[1] = a01 * 0.125f; r0[2] = a02 * 0.125f;
        r1[0] = a10 * 0.125f; r1[1] = a11 * 0.125f; r1[2] = a12 * 0.125f;
    }
    __syncthreads();

    // softmax per destination d, in-place in smem
    if (tid < G) {
        float* row = alpha + tid * G;
        float m = row[0];
        #pragma unroll
        for (int s = 1; s < G; s++) m = fmaxf(m, row[s]);
        float sum = 0.f;
        #pragma unroll
        for (int s = 0; s < G; s++) {
            float e = expf(row[s] - m);
            row[s] = e;
            sum += e;
        }
        float inv = 1.0f / (sum + 1e-16f);
        #pragma unroll
        for (int s = 0; s < G; s++) row[s] *= inv;
    }
    __syncthreads();

    // aggregate: thread = (d, cc); handles c4 = cc and cc+8; RED into g_h
    {
        int d  = tid >> 3;          // 0..23
        int cc = tid & 7;           // column group a: cc, b: cc+8
        float4 acc0 = make_float4(0.f, 0.f, 0.f, 0.f);
        float4 acc1 = make_float4(0.f, 0.f, 0.f, 0.f);
        const float* ar = alpha + d * G;
        #pragma unroll
        for (int s = 0; s < G; s++) {
            float a = ar[s];
            float4 v0 = v4h[s * 16 + cc];
            float4 v1 = v4h[s * 16 + cc + 8];
            acc0.x = fmaf(a, v0.x, acc0.x); acc0.y = fmaf(a, v0.y, acc0.y);
            acc0.z = fmaf(a, v0.z, acc0.z); acc0.w = fmaf(a, v0.w, acc0.w);
            acc1.x = fmaf(a, v1.x, acc1.x); acc1.y = fmaf(a, v1.y, acc1.y);
            acc1.z = fmaf(a, v1.z, acc1.z); acc1.w = fmaf(a, v1.w, acc1.w);
        }
        float* dst = g_h + (size_t)(n0 + d) * DH;
        atomicAdd(dst + cc * 4 + 0, acc0.x * 0.125f);
        atomicAdd(dst + cc * 4 + 1, acc0.y * 0.125f);
        atomicAdd(dst + cc * 4 + 2, acc0.z * 0.125f);
        atomicAdd(dst + cc * 4 + 3, acc0.w * 0.125f);
        atomicAdd(dst + 32 + cc * 4 + 0, acc1.x * 0.125f);
        atomicAdd(dst + 32 + cc * 4 + 1, acc1.y * 0.125f);
        atomicAdd(dst + 32 + cc * 4 + 2, acc1.z * 0.125f);
        atomicAdd(dst + 32 + cc * 4 + 3, acc1.w * 0.125f);
    }
}

// ---------------- K5: h stats (reads finished g_h, 1.57MB) ------------------
__global__ void __launch_bounds__(256)
k_hstats() {
    __shared__ float smS[16 * 64], smQ[16 * 64];
    int t  = threadIdx.x;
    int c4 = t & 15;
    int rs = t >> 4;
    int r0 = blockIdx.x * 512;

    const float4* h4 = (const float4*)g_h;
    float4 s = make_float4(0.f, 0.f, 0.f, 0.f);
    float4 q = make_float4(0.f, 0.f, 0.f, 0.f);
    #pragma unroll 4
    for (int r = rs; r < 512; r += 16) {
        float4 a = h4[(size_t)(r0 + r) * 16 + c4];
        s.x += a.x; s.y += a.y; s.z += a.z; s.w += a.w;
        q.x += a.x * a.x; q.y += a.y * a.y; q.z += a.z * a.z; q.w += a.w * a.w;
    }
    ((float4*)smS)[rs * 16 + c4] = s;
    ((float4*)smQ)[rs * 16 + c4] = q;
    __syncthreads();
    if (t < 64) {
        float ss = 0.f, qq = 0.f;
        #pragma unroll
        for (int j = 0; j < 16; j++) { ss += smS[j * 64 + t]; qq += smQ[j * 64 + t]; }
        atomicAdd(&g_hsum[t], ss);
        atomicAdd(&g_hsumsq[t], qq);
    }
}

__device__ __forceinline__ float gelu_exact(float v) {
    return 0.5f * v * (1.0f + erff(v * 0.70710678118654752f));
}

// ---------------- K6: global norm + PFF + per-set norm + score + pooling ----
#define WP 65
__global__ void __launch_bounds__(256)
k_final(const float* __restrict__ x,
        const float* __restrict__ no_w, const float* __restrict__ no_b,
        const float* __restrict__ no_ms,
        const float* __restrict__ o_w1, const float* __restrict__ o_b1,
        const float* __restrict__ o_w2, const float* __restrict__ o_b2,
        const float* __restrict__ pn_w, const float* __restrict__ pn_b,
        const float* __restrict__ pn_ms,
        const float* __restrict__ p_w1, const float* __restrict__ p_b1,
        const float* __restrict__ p_w2, const float* __restrict__ p_b2,
        float* __restrict__ out) {
    extern __shared__ float dsm[];
    float* w1T  = dsm;
    float* w2T  = w1T + 64 * WP;
    float* pw1T = w2T + 64 * WP;
    float* hs   = pw1T + 64 * WP;
    float* hn   = hs + G * DH;
    float* t1   = hn + G * DH;
    float* h2   = t1 + G * DH;
    float* a2   = h2 + G * DH;
    float* b2   = a2 + DH;
    float* cm   = b2 + DH;
    float* cr   = cm + DH;
    float* b1s  = cr + DH;
    float* b2s  = b1s + DH;
    float* pb1s = b2s + DH;
    float* pw2s = pb1s + DH;
    float* score = pw2s + DH;
    float* wsf   = score + G;

    int tid = threadIdx.x;
    int n0  = blockIdx.x * G;

    for (int i = tid; i < 64 * 64; i += 256) {
        int j = i >> 6, c = i & 63;
        w1T[c * WP + j]  = o_w1[i];
        w2T[c * WP + j]  = o_w2[i];
        pw1T[c * WP + j] = p_w1[i];
    }
    if (tid < DH) {
        b1s[tid] = o_b1[tid]; b2s[tid] = o_b2[tid];
        pb1s[tid] = p_b1[tid]; pw2s[tid] = p_w2[tid];
        const float invN = 1.0f / NN;
        float mean = g_hsum[tid] * invN;
        float ex2  = g_hsumsq[tid] * invN;
        float mm   = mean * no_ms[tid];
        float var  = ex2 - 2.f * mm * mean + mm * mm;
        float rinv = rsqrtf(var + 1e-5f);
        a2[tid] = no_w[tid] * rinv;
        b2[tid] = no_b[tid] - no_w[tid] * rinv * mm;
    }
    for (int i = tid; i < G * DH; i += 256) hs[i] = g_h[(size_t)n0 * DH + i];
    __syncthreads();

    for (int i = tid; i < G * DH; i += 256) {
        int c = i & 63;
        hn[i] = fmaf(hs[i], a2[c], b2[c]);
    }
    __syncthreads();

    for (int i = tid; i < G * DH; i += 256) {
        int d = i >> 6, j = i & 63;
        float acc = b1s[j];
        const float* hr = hn + d * DH;
        #pragma unroll 16
        for (int c = 0; c < DH; c++) acc = fmaf(hr[c], w1T[c * WP + j], acc);
        t1[i] = gelu_exact(acc);
    }
    __syncthreads();

    for (int i = tid; i < G * DH; i += 256) {
        int d = i >> 6, c = i & 63;
        float acc = b2s[c];
        const float* tr = t1 + d * DH;
        #pragma unroll 16
        for (int j = 0; j < DH; j++) acc = fmaf(tr[j], w2T[j * WP + c], acc);
        h2[i] = hs[i] + acc;
    }
    __syncthreads();

    if (tid < DH) {
        int c = tid;
        float m = 0.f;
        #pragma unroll
        for (int d = 0; d < G; d++) m += h2[d * DH + c];
        m *= (1.0f / G);
        float mm = m * pn_ms[c];
        float vv = 0.f;
        #pragma unroll
        for (int d = 0; d < G; d++) { float t = h2[d * DH + c] - mm; vv += t * t; }
        vv *= (1.0f / G);
        cm[c] = mm;
        cr[c] = pn_w[c] * rsqrtf(vv + 1e-5f);
    }
    __syncthreads();

    for (int i = tid; i < G * DH; i += 256) {
        int c = i & 63;
        hn[i] = fmaf(h2[i] - cm[c], cr[c], pn_b[c]);
    }
    __syncthreads();

    for (int i = tid; i < G * DH; i += 256) {
        int d = i >> 6, j = i & 63;
        float acc = pb1s[j];
        const float* hr = hn + d * DH;
        #pragma unroll 16
        for (int c = 0; c < DH; c++) acc = fmaf(hr[c], pw1T[c * WP + j], acc);
        t1[i] = gelu_exact(acc);
    }
    __syncthreads();

    if (tid < G) {
        float acc = p_b2[0];
        const float* tr = t1 + tid * DH;
        #pragma unroll 16
        for (int j = 0; j < DH; j++) acc = fmaf(tr[j], pw2s[j], acc);
        score[tid] = acc;
    }
    __syncthreads();

    if (tid == 0) {
        float m = score[0];
        #pragma unroll
        for (int d = 1; d < G; d++) m = fmaxf(m, score[d]);
        float sum = 0.f;
        #pragma unroll
        for (int d = 0; d < G; d++) { wsf[d] = expf(score[d] - m); sum += wsf[d]; }
        float inv = 1.0f / (sum + 1e-16f);
        #pragma unroll
        for (int d = 0; d < G; d++) wsf[d] *= inv;
    }
    __syncthreads();

    if (tid < DIN) {
        float acc = 0.f;
        #pragma unroll
        for (int d = 0; d < G; d++)
            acc = fmaf(wsf[d], x[(size_t)(n0 + d) * DIN + tid], acc);
        out[blockIdx.x * DIN + tid] = acc;
    }
}

// ---------------- launch -----------------------------------------------------
extern "C" void kernel_launch(void* const* d_in, const int* in_sizes, int n_in,
                              void* d_out, int out_size) {
    const float* x     = (const float*)d_in[0];
    const float* nq_w  = (const float*)d_in[4];
    const float* nq_b  = (const float*)d_in[5];
    const float* nq_ms = (const float*)d_in[6];
    const float* wq    = (const float*)d_in[7];
    const float* bq    = (const float*)d_in[8];
    const float* wk    = (const float*)d_in[9];
    const float* bk    = (const float*)d_in[10];
    const float* wv    = (const float*)d_in[11];
    const float* bv    = (const float*)d_in[12];
    const float* no_w  = (const float*)d_in[13];
    const float* no_b  = (const float*)d_in[14];
    const float* no_ms = (const float*)d_in[15];
    const float* o_w1  = (const float*)d_in[16];
    const float* o_b1  = (const float*)d_in[17];
    const float* o_w2  = (const float*)d_in[18];
    const float* o_b2  = (const float*)d_in[19];
    const float* pn_w  = (const float*)d_in[20];
    const float* pn_b  = (const float*)d_in[21];
    const float* pn_ms = (const float*)d_in[22];
    const float* p_w1  = (const float*)d_in[23];
    const float* p_b1  = (const float*)d_in[24];
    const float* p_w2  = (const float*)d_in[25];
    const float* p_b2  = (const float*)d_in[26];
    float* out = (float*)d_out;

    const int smem_qkv = 512 + 2 * ATILE + 2 * BTILE;                        // 104,960 B
    const int smem_fin = (3 * 64 * WP + 4 * G * DH + 8 * DH + 2 * G) * 4;    // ~77 KB
    cudaFuncSetAttribute(k_qkv,   cudaFuncAttributeMaxDynamicSharedMemorySize, smem_qkv);
    cudaFuncSetAttribute(k_final, cudaFuncAttributeMaxDynamicSharedMemorySize, smem_fin);

    k_xstats<<<96, 256>>>(x);
    k_xnorm<<<60, 256>>>(x, nq_w, nq_b, nq_ms, wq, wk, wv);
    k_qkv<<<dim3(48, 24), 256, smem_qkv>>>(bq, bk, bv);
    k_attn<<<2048, 192>>>();
    k_hstats<<<12, 256>>>();
    k_final<<<256, 256, smem_fin>>>(x, no_w, no_b, no_ms,
                                    o_w1, o_b1, o_w2, o_b2,
                                    pn_w, pn_b, pn_ms,
                                    p_w1, p_b1, p_w2, p_b2, out);
}